// round 11
// baseline (speedup 1.0000x reference)
#include <cuda_runtime.h>
#include <cuda_fp16.h>
#include <math.h>
#include <stdint.h>

#define BB 64
#define HH 1024
#define VV 2048
#define TT 256
#define GG 4096
#define NBLK 128
#define NTHR 512
#define STG 49152u   // stage stride: [Ahi0 8K][Alo0 8K][Ahi1 8K][Alo1 8K][W0 8K][W1 8K]

typedef unsigned long long u64;
typedef unsigned int u32;

// ---------------- device globals ----------------
__device__ __align__(128) unsigned char g_w0img[8u * 1024 * 1024];
__device__ __align__(128) unsigned char g_w1img[16u * 1024 * 1024];
__device__ __align__(128) unsigned char g_w2img[16u * 1024 * 1024];
__device__ __align__(128) unsigned char g_img1[2][16 * 16384];
__device__ __align__(128) unsigned char g_img2[2][16 * 16384];
__device__ __align__(128) unsigned char g_img3[2][16 * 16384];
__device__ float g_c[3][BB * HH];
__device__ float g_hfin[2][BB * HH];
__device__ float g_h3[(TT + 1) * BB * HH];
__device__ float g_part[3 * 64 * 4096];
__device__ unsigned g_flag[3 * 64];

__device__ unsigned g_count = 0;
__device__ volatile unsigned g_gen = 0;

__device__ __forceinline__ u32 swz(u32 off) { return off ^ ((off >> 3) & 0x70); }

__device__ __forceinline__ u32 smem_u32(const void* p) {
    u32 r;
    asm("{ .reg .u64 t; cvta.to.shared.u64 t, %1; cvt.u32.u64 %0, t; }" : "=r"(r) : "l"(p));
    return r;
}
__device__ __forceinline__ void mbar_init(u32 a, u32 cnt) {
    asm volatile("mbarrier.init.shared.b64 [%0], %1;" :: "r"(a), "r"(cnt) : "memory");
}
__device__ __forceinline__ void mbar_expect_tx(u32 a, u32 bytes) {
    asm volatile("mbarrier.arrive.expect_tx.shared.b64 _, [%0], %1;" :: "r"(a), "r"(bytes) : "memory");
}
__device__ __forceinline__ void mbar_wait(u32 a, u32 parity) {
    u32 done;
    asm volatile("{\n\t.reg .pred p;\n\t"
                 "mbarrier.try_wait.parity.acquire.cta.shared::cta.b64 p, [%1], %2;\n\t"
                 "selp.b32 %0, 1, 0, p;\n\t}"
                 : "=r"(done) : "r"(a), "r"(parity) : "memory");
    if (!done) {
        asm volatile("{\n\t.reg .pred P1;\n\t"
                     "W_%=:\n\t"
                     "mbarrier.try_wait.parity.acquire.cta.shared::cta.b64 P1, [%0], %1, 0x989680;\n\t"
                     "@P1 bra.uni D_%=;\n\t"
                     "bra.uni W_%=;\n\t"
                     "D_%=:\n\t}" :: "r"(a), "r"(parity) : "memory");
    }
}
__device__ __forceinline__ void bulk_g2s(u32 dst, const void* src, u32 bytes, u32 mbar) {
    asm volatile("cp.async.bulk.shared::cluster.global.mbarrier::complete_tx::bytes [%0], [%1], %2, [%3];"
                 :: "r"(dst), "l"(src), "r"(bytes), "r"(mbar) : "memory");
}

__device__ __forceinline__ void ldm4(u32 addr, u32* r) {
    asm volatile("ldmatrix.sync.aligned.m8n8.x4.shared.b16 {%0,%1,%2,%3}, [%4];"
                 : "=r"(r[0]), "=r"(r[1]), "=r"(r[2]), "=r"(r[3]) : "r"(addr));
}
__device__ __forceinline__ u32 ldm_addr(u32 tilebase, int rbase, int kq, int lane) {
    int row  = rbase + (lane & 7) + ((lane >> 3) & 1) * 8;
    int colb = kq * 32 + ((lane >> 4) & 1) * 16;
    return tilebase + swz((u32)(row * 128 + colb));
}
__device__ __forceinline__ void mma16816(float* d, const u32* a, u32 b0, u32 b1) {
    asm volatile("mma.sync.aligned.m16n8k16.row.col.f32.f16.f16.f32 "
                 "{%0,%1,%2,%3},{%4,%5,%6,%7},{%8,%9},{%0,%1,%2,%3};"
                 : "+f"(d[0]), "+f"(d[1]), "+f"(d[2]), "+f"(d[3])
                 : "r"(a[0]), "r"(a[1]), "r"(a[2]), "r"(a[3]), "r"(b0), "r"(b1));
}

// ---------------- grid barrier ----------------
__device__ __forceinline__ void gbar() {
    __syncthreads();
    if (threadIdx.x == 0) {
        unsigned gen = g_gen;
        __threadfence();
        unsigned a = atomicAdd(&g_count, 1);
        if (a == NBLK - 1) {
            atomicExch(&g_count, 0);
            __threadfence();
            g_gen = gen + 1;
        } else {
            while (g_gen == gen) { __nanosleep(32); }
            __threadfence();
        }
    }
    __syncthreads();
}

// ---------------- init ----------------
__global__ void init_zero() {
    int i = blockIdx.x * blockDim.x + threadIdx.x;
    if (i < BB * HH) {
        g_c[0][i] = 0.f; g_c[1][i] = 0.f; g_c[2][i] = 0.f;
        g_h3[i] = 0.f;
    }
    if (i < 3 * 64) g_flag[i] = 0u;
    int n32 = 16 * 16384 / 4;
    for (int j = i; j < n32; j += gridDim.x * blockDim.x) {
        ((u32*)g_img1[0])[j] = 0u;
        ((u32*)g_img2[0])[j] = 0u;
        ((u32*)g_img3[0])[j] = 0u;
    }
}

// ---------------- weight conversion (fp16, single) ----------------
__global__ void wconv(const float* __restrict__ W1, const float* __restrict__ W2,
                      const float* __restrict__ W3) {
    int l = blockIdx.y;
    size_t idx = (size_t)blockIdx.x * blockDim.x + threadIdx.x;
    int K = (l == 0) ? HH : 2 * HH;
    if (idx >= (size_t)K * GG) return;
    int k = (int)(idx >> 12);
    int n = (int)(idx & 4095);
    float w;
    if (l == 0)      w = W1[(size_t)(VV + k) * GG + n];
    else if (l == 1) w = W2[idx];
    else             w = W3[idx];
    __half hw = __float2half(w);
    int g = n >> 10, u = n & 1023;
    int nt = u >> 4, jj = u & 15;
    int nc = g * 16 + jj;
    int nch = K >> 6;
    size_t base = ((size_t)nt * nch + (k >> 6)) * 8192;
    u32 off = swz((u32)(nc * 128 + (k & 63) * 2));
    unsigned char* img = (l == 0) ? g_w0img : (l == 1) ? g_w1img : g_w2img;
    *(__half*)(img + base + off) = hw;
}

// ---------------- per-wave segment descriptors (big-chunk = 128 k) ----------------
struct Seg {
    const unsigned char* a;
    const unsigned char* wgt;
    int start;   // in big-chunk units
    int nch;     // big chunks
    int l, t;
};

__device__ __forceinline__ void make_seg(Seg& s, int l, int t, int nt, int kh) {
    if (l == 0) {
        s.nch = 4;
        s.wgt = g_w0img + ((size_t)nt * 16 + (size_t)kh * 8) * 8192;
        s.a   = g_img1[t & 1] + (size_t)(kh * 8) * 16384;
    } else if (l == 1) {
        s.nch = 8;
        s.wgt = g_w1img + ((size_t)nt * 32 + (size_t)kh * 16) * 8192;
        s.a   = kh ? g_img2[t & 1] : g_img1[(t + 1) & 1];
    } else {
        s.nch = 8;
        s.wgt = g_w2img + ((size_t)nt * 32 + (size_t)kh * 16) * 8192;
        s.a   = kh ? g_img3[t & 1] : g_img2[(t + 1) & 1];
    }
    s.l = l; s.t = t;
}

// issue one big chunk's bulk loads (elected thread only): A 32KB + W 16KB
__device__ __forceinline__ void issue_chunk(u32 sb, u32 sbar, const Seg* segs, int ns,
                                            int g, u32 gg) {
    int s = 0;
    while (s < ns - 1 && g >= segs[s + 1].start) s++;
    int c = g - segs[s].start;
    const unsigned char* at = segs[s].a   + (size_t)c * 32768;
    const unsigned char* wt = segs[s].wgt + (size_t)c * 16384;
    u32 st = (gg + (u32)g) & 3u;
    u32 mb = sbar + st * 8;
    mbar_expect_tx(mb, 49152);
    bulk_g2s(sb + st * STG,          at, 32768, mb);
    bulk_g2s(sb + st * STG + 32768,  wt, 16384, mb);
}

// ---------------- persistent wavefront LSTM (512 threads, big chunks) ----------------
__global__ void __launch_bounds__(NTHR, 1) lstm_persist(
    const int*   __restrict__ X,
    const float* __restrict__ W1,
    const float* __restrict__ b1, const float* __restrict__ b2, const float* __restrict__ b3)
{
    extern __shared__ unsigned char dynsm[];
    u32 raw = smem_u32(dynsm);
    u32 sb = (raw + 127u) & ~127u;
    float* Sm = (float*)(dynsm + (sb - raw) + 4 * STG);   // [64 c][65 m] = 16640B
    u32 sbar = sb + 4 * STG + 16640;                      // 4 mbarriers

    const int tid  = threadIdx.x;
    const int wid  = tid >> 5;
    const int lane = tid & 31;
    const int bid  = blockIdx.x;
    const int nt   = bid >> 1;
    const int kh   = bid & 1;
    const int j0   = nt * 16;
    const int mt   = wid >> 2;        // 0..3
    const int nq   = wid & 3;         // 0..3
    const int m0   = mt * 16;
    const int nb   = nq * 16;

    if (tid == 0) {
#pragma unroll
        for (int s = 0; s < 4; s++) mbar_init(sbar + s * 8, 1);
    }
    __syncthreads();

    u32 gg = 0;   // persistent big-chunk counter

    for (int w = 0; w < TT + 2; w++) {
        Seg segs[3];
        int ns = 0, total = 0;
#pragma unroll
        for (int l = 0; l < 3; l++) {
            int t = w - l;
            if (t >= 0 && t < TT) {
                make_seg(segs[ns], l, t, nt, kh);
                segs[ns].start = total;
                total += segs[ns].nch;
                ns++;
            }
        }

        if (tid == 0) {
#pragma unroll
            for (int i = 0; i < 3; i++)
                if (i < total) issue_chunk(sb, sbar, segs, ns, i, gg);
        }

        int g = 0;
        for (int s = 0; s < ns; s++) {
            float acc[2][4];
#pragma unroll
            for (int i = 0; i < 2; i++)
#pragma unroll
                for (int q = 0; q < 4; q++) acc[i][q] = 0.f;

            const int nch = segs[s].nch;
            for (int c = 0; c < nch; c++) {
                __syncthreads();   // all warps done reading stage (g-1)&3
                if (tid == 0 && g + 3 < total)
                    issue_chunk(sb, sbar, segs, ns, g + 3, gg);

                u32 cur = (gg + (u32)g) & 3u;
                mbar_wait(sbar + cur * 8, ((gg + (u32)g) >> 2) & 1u);

                u32 stg = sb + cur * STG;
#pragma unroll
                for (int half = 0; half < 2; half++) {
                    u32 Ahi = stg + (u32)half * 16384;
                    u32 Alo = Ahi + 8192;
                    u32 Wt  = stg + 32768 + (u32)half * 8192;
#pragma unroll
                    for (int kq = 0; kq < 4; kq++) {
                        u32 ah[4], al[4], b[4];
                        ldm4(ldm_addr(Ahi, m0, kq, lane), ah);
                        ldm4(ldm_addr(Alo, m0, kq, lane), al);
                        ldm4(ldm_addr(Wt, nb, kq, lane), b);
                        mma16816(acc[0], ah, b[0], b[2]);
                        mma16816(acc[1], ah, b[1], b[3]);
                        mma16816(acc[0], al, b[0], b[2]);
                        mma16816(acc[1], al, b[1], b[3]);
                    }
                }
                g++;
            }

            // ---- epilogue: K-half exchange + gates ----
            const int l = segs[s].l;
            const int t = segs[s].t;
            const int owner = (l == 1) ? 1 : 0;
            float* pbase = g_part + ((size_t)l * 64 + nt) * 4096;
            unsigned* flag = &g_flag[l * 64 + nt];

            if (kh != owner) {
                float4* pp4 = (float4*)pbase;
#pragma unroll
                for (int nti = 0; nti < 2; nti++) {
                    float4 v = make_float4(acc[nti][0], acc[nti][1], acc[nti][2], acc[nti][3]);
                    __stcg(&pp4[tid * 2 + nti], v);
                }
                __threadfence();
                __syncthreads();
                if (tid == 0) atomicExch(flag, (unsigned)(t + 1));
            } else {
                if (tid == 0) {
                    while (*(volatile unsigned*)flag != (unsigned)(t + 1)) __nanosleep(16);
                    __threadfence();
                }
                __syncthreads();
                const float4* pp4 = (const float4*)pbase;
#pragma unroll
                for (int nti = 0; nti < 2; nti++) {
                    float4 v = __ldcg(&pp4[tid * 2 + nti]);
                    acc[nti][0] += v.x; acc[nti][1] += v.y;
                    acc[nti][2] += v.z; acc[nti][3] += v.w;
                }
                {
                    int gid = lane >> 2, tig = lane & 3;
                    int mrow = m0 + gid;
#pragma unroll
                    for (int nti = 0; nti < 2; nti++) {
                        int cc = nb + nti * 8 + tig * 2;
                        Sm[cc * 65 + mrow]           = acc[nti][0];
                        Sm[(cc + 1) * 65 + mrow]     = acc[nti][1];
                        Sm[cc * 65 + mrow + 8]       = acc[nti][2];
                        Sm[(cc + 1) * 65 + mrow + 8] = acc[nti][3];
                    }
                }
                __syncthreads();

                const float* bias = (l == 0) ? b1 : (l == 1) ? b2 : b3;
                float* cbuf = g_c[l];
                unsigned char* imgout = (l == 0) ? g_img1[(t + 1) & 1]
                                      : (l == 1) ? g_img2[(t + 1) & 1]
                                                 : g_img3[(t + 1) & 1];
#pragma unroll
                for (int i = 0; i < 2; i++) {
                    int e  = tid + i * 512;
                    int m  = e & 63;
                    int jj = e >> 6;
                    int jg = j0 + jj;
                    float f  = Sm[jj * 65 + m]        + bias[jg];
                    float ig = Sm[(16 + jj) * 65 + m] + bias[HH + jg];
                    float og = Sm[(32 + jj) * 65 + m] + bias[2 * HH + jg];
                    float ct = Sm[(48 + jj) * 65 + m] + bias[3 * HH + jg];
                    if (l == 0) {
                        int xid = X[m * TT + t];
                        const float* wrow = W1 + (size_t)xid * GG + jg;
                        f  += wrow[0];
                        ig += wrow[HH];
                        og += wrow[2 * HH];
                        ct += wrow[3 * HH];
                    }
                    int cidx = m * HH + jg;
                    float cv = cbuf[cidx];
                    float sf = 1.f / (1.f + __expf(-f));
                    float si = 1.f / (1.f + __expf(-ig));
                    float so = 1.f / (1.f + __expf(-og));
                    float cn = sf * cv + si * tanhf(ct);
                    float hn = so * tanhf(cn);
                    cbuf[cidx] = cn;

                    __half hi = __float2half(hn);
                    __half lo = __float2half(hn - __half2float(hi));
                    unsigned char* cb = imgout + (size_t)(jg >> 6) * 16384;
                    u32 off = swz((u32)(m * 128 + (jg & 63) * 2));
                    *(__half*)(cb + off)        = hi;
                    *(__half*)(cb + 8192 + off) = lo;

                    if (l == 2) g_h3[(size_t)(t + 1) * BB * HH + cidx] = hn;
                    else if (t == TT - 1) g_hfin[l][cidx] = hn;
                }
            }
        }
        gg += (u32)total;
        gbar();
    }
}

// ---------------- out GEMM (f32x2 SIMT) ----------------
__device__ __forceinline__ u64 ffma2(u64 a, u64 b, u64 c) {
    u64 d; asm("fma.rn.f32x2 %0, %1, %2, %3;" : "=l"(d) : "l"(a), "l"(b), "l"(c)); return d;
}
__device__ __forceinline__ u64 splat2(float w) {
    u64 d; asm("mov.b64 %0, {%1, %1};" : "=l"(d) : "f"(w)); return d;
}
__device__ __forceinline__ void unpack2(u64 v, float& lo, float& hi) {
    asm("mov.b64 {%0, %1}, %2;" : "=f"(lo), "=f"(hi) : "l"(v));
}

__global__ void __launch_bounds__(128) out_gemm(
    const float* __restrict__ Wout, const float* __restrict__ bout, float* __restrict__ out)
{
    const float* Amat = g_h3 + BB * HH;
    __shared__ __align__(16) float As[32][68];
    __shared__ __align__(16) float Ws[32][64];
    const int tid = threadIdx.x;
    const int n0 = blockIdx.x * 64;
    const int m0 = blockIdx.y * 64;
    const int tx = tid & 15;
    const int ty = tid >> 4;

    u64 acc[4][4];
#pragma unroll
    for (int pr = 0; pr < 4; pr++)
#pragma unroll
        for (int c = 0; c < 4; c++) acc[pr][c] = splat2(bout[n0 + tx * 4 + c]);

    for (int kc = 0; kc < HH; kc += 32) {
#pragma unroll
        for (int i = 0; i < 16; i++) {
            int idx = tid + i * 128;
            int r = idx >> 5, kk = idx & 31;
            As[kk][r] = Amat[(size_t)(m0 + r) * HH + kc + kk];
        }
#pragma unroll
        for (int i = 0; i < 16; i++) {
            int idx = tid + i * 128;
            int kk = idx >> 6, n = idx & 63;
            Ws[kk][n] = Wout[(size_t)(kc + kk) * VV + n0 + n];
        }
        __syncthreads();
#pragma unroll
        for (int kk = 0; kk < 32; kk++) {
            double2 xa = *(const double2*)&As[kk][ty * 8];
            double2 xb = *(const double2*)&As[kk][ty * 8 + 4];
            float4  wf = *(const float4*)&Ws[kk][tx * 4];
            u64 xp[4] = { __double_as_longlong(xa.x), __double_as_longlong(xa.y),
                          __double_as_longlong(xb.x), __double_as_longlong(xb.y) };
            u64 w0 = splat2(wf.x), w1 = splat2(wf.y), w2 = splat2(wf.z), w3 = splat2(wf.w);
#pragma unroll
            for (int pr = 0; pr < 4; pr++) {
                acc[pr][0] = ffma2(xp[pr], w0, acc[pr][0]);
                acc[pr][1] = ffma2(xp[pr], w1, acc[pr][1]);
                acc[pr][2] = ffma2(xp[pr], w2, acc[pr][2]);
                acc[pr][3] = ffma2(xp[pr], w3, acc[pr][3]);
            }
        }
        __syncthreads();
    }
#pragma unroll
    for (int pr = 0; pr < 4; pr++) {
        float lo[4], hi[4];
#pragma unroll
        for (int c = 0; c < 4; c++) unpack2(acc[pr][c], lo[c], hi[c]);
        int m = m0 + ty * 8 + pr * 2;
        *(float4*)&out[(size_t)m * VV + n0 + tx * 4]       = make_float4(lo[0], lo[1], lo[2], lo[3]);
        *(float4*)&out[(size_t)(m + 1) * VV + n0 + tx * 4] = make_float4(hi[0], hi[1], hi[2], hi[3]);
    }
}

__global__ void copy_states(float* __restrict__ out) {
    int i = blockIdx.x * blockDim.x + threadIdx.x;
    if (i < BB * HH) {
        out[0 * BB * HH + i] = g_hfin[0][i];
        out[1 * BB * HH + i] = g_c[0][i];
        out[2 * BB * HH + i] = g_hfin[1][i];
        out[3 * BB * HH + i] = g_c[1][i];
        out[4 * BB * HH + i] = g_h3[(size_t)TT * BB * HH + i];
        out[5 * BB * HH + i] = g_c[2][i];
    }
}

// ---------------- launch ----------------
extern "C" void kernel_launch(void* const* d_in, const int* in_sizes, int n_in,
                              void* d_out, int out_size) {
    const int*   X    = (const int*)  d_in[0];
    const float* W1   = (const float*)d_in[1];
    const float* b1   = (const float*)d_in[2];
    const float* W2   = (const float*)d_in[3];
    const float* b2   = (const float*)d_in[4];
    const float* W3   = (const float*)d_in[5];
    const float* b3   = (const float*)d_in[6];
    const float* Wout = (const float*)d_in[7];
    const float* bout = (const float*)d_in[8];
    float* out = (float*)d_out;
    (void)in_sizes; (void)n_in;

    static int attr_done = 0;
    if (!attr_done) {
        cudaFuncSetAttribute(lstm_persist, cudaFuncAttributeMaxDynamicSharedMemorySize, 213504);
        attr_done = 1;
    }

    init_zero<<<256, 256>>>();

    dim3 wgrid((2u * HH * GG + 255) / 256, 3);
    wconv<<<wgrid, 256>>>(W1, W2, W3);

    lstm_persist<<<NBLK, NTHR, 213504>>>(X, W1, b1, b2, b3);

    dim3 out_grid(VV / 64, (TT * BB) / 64);
    out_gemm<<<out_grid, 128>>>(Wout, bout, out);

    long long need = (long long)TT * BB * VV + 6LL * BB * HH;
    if ((long long)out_size >= need) {
        copy_states<<<(BB * HH + 255) / 256, 256>>>(out + (size_t)TT * BB * VV);
    }
}

// round 12
// speedup vs baseline: 1.1252x; 1.1252x over previous
#include <cuda_runtime.h>
#include <cuda_fp16.h>
#include <math.h>
#include <stdint.h>

#define BB 64
#define HH 1024
#define VV 2048
#define TT 256
#define GG 4096
#define NBLK 128
#define NTHR 512
#define STG 16384u   // stage stride: [A 8K][W 8K]
#define NST 8        // pipeline stages

typedef unsigned long long u64;
typedef unsigned int u32;

// ---------------- device globals ----------------
__device__ __align__(128) unsigned char g_w0img[8u * 1024 * 1024];
__device__ __align__(128) unsigned char g_w1img[16u * 1024 * 1024];
__device__ __align__(128) unsigned char g_w2img[16u * 1024 * 1024];
// A images: fp16 single, per kchunk 8KB tile [64 m][64 k], SW128-swizzled
__device__ __align__(128) unsigned char g_img1[2][16 * 8192];
__device__ __align__(128) unsigned char g_img2[2][16 * 8192];
__device__ __align__(128) unsigned char g_img3[2][16 * 8192];
__device__ float g_c[3][BB * HH];
__device__ float g_hfin[2][BB * HH];
__device__ float g_h3[(TT + 1) * BB * HH];
__device__ float g_part[3 * 64 * 4096];
__device__ unsigned g_flag[3 * 64];

__device__ unsigned g_count = 0;
__device__ volatile unsigned g_gen = 0;

__device__ __forceinline__ u32 swz(u32 off) { return off ^ ((off >> 3) & 0x70); }

__device__ __forceinline__ u32 smem_u32(const void* p) {
    u32 r;
    asm("{ .reg .u64 t; cvta.to.shared.u64 t, %1; cvt.u32.u64 %0, t; }" : "=r"(r) : "l"(p));
    return r;
}
__device__ __forceinline__ void mbar_init(u32 a, u32 cnt) {
    asm volatile("mbarrier.init.shared.b64 [%0], %1;" :: "r"(a), "r"(cnt) : "memory");
}
__device__ __forceinline__ void mbar_expect_tx(u32 a, u32 bytes) {
    asm volatile("mbarrier.arrive.expect_tx.shared.b64 _, [%0], %1;" :: "r"(a), "r"(bytes) : "memory");
}
__device__ __forceinline__ void mbar_wait(u32 a, u32 parity) {
    u32 done;
    asm volatile("{\n\t.reg .pred p;\n\t"
                 "mbarrier.try_wait.parity.acquire.cta.shared::cta.b64 p, [%1], %2;\n\t"
                 "selp.b32 %0, 1, 0, p;\n\t}"
                 : "=r"(done) : "r"(a), "r"(parity) : "memory");
    if (!done) {
        asm volatile("{\n\t.reg .pred P1;\n\t"
                     "W_%=:\n\t"
                     "mbarrier.try_wait.parity.acquire.cta.shared::cta.b64 P1, [%0], %1, 0x989680;\n\t"
                     "@P1 bra.uni D_%=;\n\t"
                     "bra.uni W_%=;\n\t"
                     "D_%=:\n\t}" :: "r"(a), "r"(parity) : "memory");
    }
}
__device__ __forceinline__ void bulk_g2s(u32 dst, const void* src, u32 bytes, u32 mbar) {
    asm volatile("cp.async.bulk.shared::cluster.global.mbarrier::complete_tx::bytes [%0], [%1], %2, [%3];"
                 :: "r"(dst), "l"(src), "r"(bytes), "r"(mbar) : "memory");
}

__device__ __forceinline__ void ldm4(u32 addr, u32* r) {
    asm volatile("ldmatrix.sync.aligned.m8n8.x4.shared.b16 {%0,%1,%2,%3}, [%4];"
                 : "=r"(r[0]), "=r"(r[1]), "=r"(r[2]), "=r"(r[3]) : "r"(addr));
}
__device__ __forceinline__ u32 ldm_addr(u32 tilebase, int rbase, int kq, int lane) {
    int row  = rbase + (lane & 7) + ((lane >> 3) & 1) * 8;
    int colb = kq * 32 + ((lane >> 4) & 1) * 16;
    return tilebase + swz((u32)(row * 128 + colb));
}
__device__ __forceinline__ void mma16816(float* d, const u32* a, u32 b0, u32 b1) {
    asm volatile("mma.sync.aligned.m16n8k16.row.col.f32.f16.f16.f32 "
                 "{%0,%1,%2,%3},{%4,%5,%6,%7},{%8,%9},{%0,%1,%2,%3};"
                 : "+f"(d[0]), "+f"(d[1]), "+f"(d[2]), "+f"(d[3])
                 : "r"(a[0]), "r"(a[1]), "r"(a[2]), "r"(a[3]), "r"(b0), "r"(b1));
}

// ---------------- grid barrier ----------------
__device__ __forceinline__ void gbar() {
    __syncthreads();
    if (threadIdx.x == 0) {
        unsigned gen = g_gen;
        __threadfence();
        unsigned a = atomicAdd(&g_count, 1);
        if (a == NBLK - 1) {
            atomicExch(&g_count, 0);
            __threadfence();
            g_gen = gen + 1;
        } else {
            while (g_gen == gen) { __nanosleep(32); }
            __threadfence();
        }
    }
    __syncthreads();
}

// ---------------- init ----------------
__global__ void init_zero() {
    int i = blockIdx.x * blockDim.x + threadIdx.x;
    if (i < BB * HH) {
        g_c[0][i] = 0.f; g_c[1][i] = 0.f; g_c[2][i] = 0.f;
        g_h3[i] = 0.f;
    }
    if (i < 3 * 64) g_flag[i] = 0u;
    int n32 = 16 * 8192 / 4;
    for (int j = i; j < n32; j += gridDim.x * blockDim.x) {
        ((u32*)g_img1[0])[j] = 0u;
        ((u32*)g_img2[0])[j] = 0u;
        ((u32*)g_img3[0])[j] = 0u;
    }
}

// ---------------- weight conversion (fp16, single) ----------------
__global__ void wconv(const float* __restrict__ W1, const float* __restrict__ W2,
                      const float* __restrict__ W3) {
    int l = blockIdx.y;
    size_t idx = (size_t)blockIdx.x * blockDim.x + threadIdx.x;
    int K = (l == 0) ? HH : 2 * HH;
    if (idx >= (size_t)K * GG) return;
    int k = (int)(idx >> 12);
    int n = (int)(idx & 4095);
    float w;
    if (l == 0)      w = W1[(size_t)(VV + k) * GG + n];
    else if (l == 1) w = W2[idx];
    else             w = W3[idx];
    __half hw = __float2half(w);
    int g = n >> 10, u = n & 1023;
    int nt = u >> 4, jj = u & 15;
    int nc = g * 16 + jj;
    int nch = K >> 6;
    size_t base = ((size_t)nt * nch + (k >> 6)) * 8192;
    u32 off = swz((u32)(nc * 128 + (k & 63) * 2));
    unsigned char* img = (l == 0) ? g_w0img : (l == 1) ? g_w1img : g_w2img;
    *(__half*)(img + base + off) = hw;
}

// ---------------- per-wave segment descriptors ----------------
struct Seg {
    const unsigned char* a;
    const unsigned char* wgt;
    int start;
    int nch;
    int l, t;
};

__device__ __forceinline__ void make_seg(Seg& s, int l, int t, int nt, int kh) {
    if (l == 0) {
        s.nch = 8;
        s.wgt = g_w0img + ((size_t)nt * 16 + (size_t)kh * 8) * 8192;
        s.a   = g_img1[t & 1] + (size_t)(kh * 8) * 8192;
    } else if (l == 1) {
        s.nch = 16;
        s.wgt = g_w1img + ((size_t)nt * 32 + (size_t)kh * 16) * 8192;
        s.a   = kh ? g_img2[t & 1] : g_img1[(t + 1) & 1];
    } else {
        s.nch = 16;
        s.wgt = g_w2img + ((size_t)nt * 32 + (size_t)kh * 16) * 8192;
        s.a   = kh ? g_img3[t & 1] : g_img2[(t + 1) & 1];
    }
    s.l = l; s.t = t;
}

// issue one chunk's bulk loads (elected thread only): A 8KB + W 8KB
__device__ __forceinline__ void issue_chunk(u32 sb, u32 sbar, const Seg* segs, int ns,
                                            int g, u32 gg) {
    int s = 0;
    while (s < ns - 1 && g >= segs[s + 1].start) s++;
    int c = g - segs[s].start;
    const unsigned char* at = segs[s].a   + (size_t)c * 8192;
    const unsigned char* wt = segs[s].wgt + (size_t)c * 8192;
    u32 st = (gg + (u32)g) & (NST - 1u);
    u32 mb = sbar + st * 8;
    mbar_expect_tx(mb, 16384);
    bulk_g2s(sb + st * STG,         at, 8192, mb);
    bulk_g2s(sb + st * STG + 8192,  wt, 8192, mb);
}

// ---------------- persistent wavefront LSTM (fp16 single-term, 8-stage ring) ----------------
__global__ void __launch_bounds__(NTHR, 1) lstm_persist(
    const int*   __restrict__ X,
    const float* __restrict__ W1,
    const float* __restrict__ b1, const float* __restrict__ b2, const float* __restrict__ b3)
{
    extern __shared__ unsigned char dynsm[];
    u32 raw = smem_u32(dynsm);
    u32 sb = (raw + 127u) & ~127u;
    float* Sm = (float*)(dynsm + (sb - raw) + NST * STG);   // [64 c][65 m] = 16640B
    u32 sbar = sb + NST * STG + 16640;                      // 8 mbarriers

    const int tid  = threadIdx.x;
    const int wid  = tid >> 5;
    const int lane = tid & 31;
    const int bid  = blockIdx.x;
    const int nt   = bid >> 1;
    const int kh   = bid & 1;
    const int j0   = nt * 16;
    const int mt   = wid >> 2;        // 0..3
    const int nq   = wid & 3;         // 0..3
    const int m0   = mt * 16;
    const int nb   = nq * 16;

    if (tid == 0) {
#pragma unroll
        for (int s = 0; s < NST; s++) mbar_init(sbar + s * 8, 1);
    }
    __syncthreads();

    u32 gg = 0;   // persistent chunk counter

    for (int w = 0; w < TT + 2; w++) {
        Seg segs[3];
        int ns = 0, total = 0;
#pragma unroll
        for (int l = 0; l < 3; l++) {
            int t = w - l;
            if (t >= 0 && t < TT) {
                make_seg(segs[ns], l, t, nt, kh);
                segs[ns].start = total;
                total += segs[ns].nch;
                ns++;
            }
        }

        // preload up to NST-1 stages
        if (tid == 0) {
#pragma unroll
            for (int i = 0; i < NST - 1; i++)
                if (i < total) issue_chunk(sb, sbar, segs, ns, i, gg);
        }

        int g = 0;
        for (int s = 0; s < ns; s++) {
            float acc[2][4];
#pragma unroll
            for (int i = 0; i < 2; i++)
#pragma unroll
                for (int q = 0; q < 4; q++) acc[i][q] = 0.f;

            const int nch = segs[s].nch;
            for (int c = 0; c < nch; c++) {
                __syncthreads();   // all warps done reading stage (g-1)&(NST-1)
                if (tid == 0 && g + NST - 1 < total)
                    issue_chunk(sb, sbar, segs, ns, g + NST - 1, gg);

                u32 gc  = gg + (u32)g;
                u32 cur = gc & (NST - 1u);
                mbar_wait(sbar + cur * 8, (gc >> 3) & 1u);

                u32 At = sb + cur * STG;
                u32 Wt = At + 8192;
#pragma unroll
                for (int kq = 0; kq < 4; kq++) {
                    u32 a[4], b[4];
                    ldm4(ldm_addr(At, m0, kq, lane), a);
                    ldm4(ldm_addr(Wt, nb, kq, lane), b);
                    mma16816(acc[0], a, b[0], b[2]);
                    mma16816(acc[1], a, b[1], b[3]);
                }
                g++;
            }

            // ---- epilogue: K-half exchange + gates ----
            const int l = segs[s].l;
            const int t = segs[s].t;
            const int owner = (l == 1) ? 1 : 0;
            float* pbase = g_part + ((size_t)l * 64 + nt) * 4096;
            unsigned* flag = &g_flag[l * 64 + nt];

            if (kh != owner) {
                float4* pp4 = (float4*)pbase;
#pragma unroll
                for (int nti = 0; nti < 2; nti++) {
                    float4 v = make_float4(acc[nti][0], acc[nti][1], acc[nti][2], acc[nti][3]);
                    __stcg(&pp4[tid * 2 + nti], v);
                }
                __threadfence();
                __syncthreads();
                if (tid == 0) atomicExch(flag, (unsigned)(t + 1));
            } else {
                if (tid == 0) {
                    while (*(volatile unsigned*)flag != (unsigned)(t + 1)) __nanosleep(16);
                    __threadfence();
                }
                __syncthreads();
                const float4* pp4 = (const float4*)pbase;
#pragma unroll
                for (int nti = 0; nti < 2; nti++) {
                    float4 v = __ldcg(&pp4[tid * 2 + nti]);
                    acc[nti][0] += v.x; acc[nti][1] += v.y;
                    acc[nti][2] += v.z; acc[nti][3] += v.w;
                }
                {
                    int gid = lane >> 2, tig = lane & 3;
                    int mrow = m0 + gid;
#pragma unroll
                    for (int nti = 0; nti < 2; nti++) {
                        int cc = nb + nti * 8 + tig * 2;
                        Sm[cc * 65 + mrow]           = acc[nti][0];
                        Sm[(cc + 1) * 65 + mrow]     = acc[nti][1];
                        Sm[cc * 65 + mrow + 8]       = acc[nti][2];
                        Sm[(cc + 1) * 65 + mrow + 8] = acc[nti][3];
                    }
                }
                __syncthreads();

                const float* bias = (l == 0) ? b1 : (l == 1) ? b2 : b3;
                float* cbuf = g_c[l];
                unsigned char* imgout = (l == 0) ? g_img1[(t + 1) & 1]
                                      : (l == 1) ? g_img2[(t + 1) & 1]
                                                 : g_img3[(t + 1) & 1];
#pragma unroll
                for (int i = 0; i < 2; i++) {
                    int e  = tid + i * 512;
                    int m  = e & 63;
                    int jj = e >> 6;
                    int jg = j0 + jj;
                    float f  = Sm[jj * 65 + m]        + bias[jg];
                    float ig = Sm[(16 + jj) * 65 + m] + bias[HH + jg];
                    float og = Sm[(32 + jj) * 65 + m] + bias[2 * HH + jg];
                    float ct = Sm[(48 + jj) * 65 + m] + bias[3 * HH + jg];
                    if (l == 0) {
                        int xid = X[m * TT + t];
                        const float* wrow = W1 + (size_t)xid * GG + jg;
                        f  += wrow[0];
                        ig += wrow[HH];
                        og += wrow[2 * HH];
                        ct += wrow[3 * HH];
                    }
                    int cidx = m * HH + jg;
                    float cv = cbuf[cidx];
                    float sf = 1.f / (1.f + __expf(-f));
                    float si = 1.f / (1.f + __expf(-ig));
                    float so = 1.f / (1.f + __expf(-og));
                    float cn = sf * cv + si * tanhf(ct);
                    float hn = so * tanhf(cn);
                    cbuf[cidx] = cn;

                    __half hv = __float2half(hn);
                    unsigned char* cb = imgout + (size_t)(jg >> 6) * 8192;
                    u32 off = swz((u32)(m * 128 + (jg & 63) * 2));
                    *(__half*)(cb + off) = hv;

                    if (l == 2) g_h3[(size_t)(t + 1) * BB * HH + cidx] = hn;
                    else if (t == TT - 1) g_hfin[l][cidx] = hn;
                }
            }
        }
        gg += (u32)total;
        gbar();
    }
}

// ---------------- out GEMM (f32x2 SIMT) ----------------
__device__ __forceinline__ u64 ffma2(u64 a, u64 b, u64 c) {
    u64 d; asm("fma.rn.f32x2 %0, %1, %2, %3;" : "=l"(d) : "l"(a), "l"(b), "l"(c)); return d;
}
__device__ __forceinline__ u64 splat2(float w) {
    u64 d; asm("mov.b64 %0, {%1, %1};" : "=l"(d) : "f"(w)); return d;
}
__device__ __forceinline__ void unpack2(u64 v, float& lo, float& hi) {
    asm("mov.b64 {%0, %1}, %2;" : "=f"(lo), "=f"(hi) : "l"(v));
}

__global__ void __launch_bounds__(128) out_gemm(
    const float* __restrict__ Wout, const float* __restrict__ bout, float* __restrict__ out)
{
    const float* Amat = g_h3 + BB * HH;
    __shared__ __align__(16) float As[32][68];
    __shared__ __align__(16) float Ws[32][64];
    const int tid = threadIdx.x;
    const int n0 = blockIdx.x * 64;
    const int m0 = blockIdx.y * 64;
    const int tx = tid & 15;
    const int ty = tid >> 4;

    u64 acc[4][4];
#pragma unroll
    for (int pr = 0; pr < 4; pr++)
#pragma unroll
        for (int c = 0; c < 4; c++) acc[pr][c] = splat2(bout[n0 + tx * 4 + c]);

    for (int kc = 0; kc < HH; kc += 32) {
#pragma unroll
        for (int i = 0; i < 16; i++) {
            int idx = tid + i * 128;
            int r = idx >> 5, kk = idx & 31;
            As[kk][r] = Amat[(size_t)(m0 + r) * HH + kc + kk];
        }
#pragma unroll
        for (int i = 0; i < 16; i++) {
            int idx = tid + i * 128;
            int kk = idx >> 6, n = idx & 63;
            Ws[kk][n] = Wout[(size_t)(kc + kk) * VV + n0 + n];
        }
        __syncthreads();
#pragma unroll
        for (int kk = 0; kk < 32; kk++) {
            double2 xa = *(const double2*)&As[kk][ty * 8];
            double2 xb = *(const double2*)&As[kk][ty * 8 + 4];
            float4  wf = *(const float4*)&Ws[kk][tx * 4];
            u64 xp[4] = { __double_as_longlong(xa.x), __double_as_longlong(xa.y),
                          __double_as_longlong(xb.x), __double_as_longlong(xb.y) };
            u64 w0 = splat2(wf.x), w1 = splat2(wf.y), w2 = splat2(wf.z), w3 = splat2(wf.w);
#pragma unroll
            for (int pr = 0; pr < 4; pr++) {
                acc[pr][0] = ffma2(xp[pr], w0, acc[pr][0]);
                acc[pr][1] = ffma2(xp[pr], w1, acc[pr][1]);
                acc[pr][2] = ffma2(xp[pr], w2, acc[pr][2]);
                acc[pr][3] = ffma2(xp[pr], w3, acc[pr][3]);
            }
        }
        __syncthreads();
    }
#pragma unroll
    for (int pr = 0; pr < 4; pr++) {
        float lo[4], hi[4];
#pragma unroll
        for (int c = 0; c < 4; c++) unpack2(acc[pr][c], lo[c], hi[c]);
        int m = m0 + ty * 8 + pr * 2;
        *(float4*)&out[(size_t)m * VV + n0 + tx * 4]       = make_float4(lo[0], lo[1], lo[2], lo[3]);
        *(float4*)&out[(size_t)(m + 1) * VV + n0 + tx * 4] = make_float4(hi[0], hi[1], hi[2], hi[3]);
    }
}

__global__ void copy_states(float* __restrict__ out) {
    int i = blockIdx.x * blockDim.x + threadIdx.x;
    if (i < BB * HH) {
        out[0 * BB * HH + i] = g_hfin[0][i];
        out[1 * BB * HH + i] = g_c[0][i];
        out[2 * BB * HH + i] = g_hfin[1][i];
        out[3 * BB * HH + i] = g_c[1][i];
        out[4 * BB * HH + i] = g_h3[(size_t)TT * BB * HH + i];
        out[5 * BB * HH + i] = g_c[2][i];
    }
}

// ---------------- launch ----------------
extern "C" void kernel_launch(void* const* d_in, const int* in_sizes, int n_in,
                              void* d_out, int out_size) {
    const int*   X    = (const int*)  d_in[0];
    const float* W1   = (const float*)d_in[1];
    const float* b1   = (const float*)d_in[2];
    const float* W2   = (const float*)d_in[3];
    const float* b2   = (const float*)d_in[4];
    const float* W3   = (const float*)d_in[5];
    const float* b3   = (const float*)d_in[6];
    const float* Wout = (const float*)d_in[7];
    const float* bout = (const float*)d_in[8];
    float* out = (float*)d_out;
    (void)in_sizes; (void)n_in;

    static int attr_done = 0;
    if (!attr_done) {
        cudaFuncSetAttribute(lstm_persist, cudaFuncAttributeMaxDynamicSharedMemorySize, 148096);
        attr_done = 1;
    }

    init_zero<<<256, 256>>>();

    dim3 wgrid((2u * HH * GG + 255) / 256, 3);
    wconv<<<wgrid, 256>>>(W1, W2, W3);

    lstm_persist<<<NBLK, NTHR, 148096>>>(X, W1, b1, b2, b3);

    dim3 out_grid(VV / 64, (TT * BB) / 64);
    out_gemm<<<out_grid, 128>>>(Wout, bout, out);

    long long need = (long long)TT * BB * VV + 6LL * BB * HH;
    if ((long long)out_size >= need) {
        copy_states<<<(BB * HH + 255) / 256, 256>>>(out + (size_t)TT * BB * VV);
    }
}

// round 13
// speedup vs baseline: 1.1731x; 1.0425x over previous
#include <cuda_runtime.h>
#include <cuda_fp16.h>
#include <math.h>
#include <stdint.h>

#define BB 64
#define HH 1024
#define VV 2048
#define TT 256
#define GG 4096
#define NBLK 128
#define NTHR 512
#define STG 16384u   // stage stride: [A 8K][W 8K]
#define NST 8        // pipeline stages

typedef unsigned long long u64;
typedef unsigned int u32;

// ---------------- device globals ----------------
__device__ __align__(128) unsigned char g_w0img[8u * 1024 * 1024];
__device__ __align__(128) unsigned char g_w1img[16u * 1024 * 1024];
__device__ __align__(128) unsigned char g_w2img[16u * 1024 * 1024];
__device__ __align__(128) unsigned char g_img1[2][16 * 8192];
__device__ __align__(128) unsigned char g_img2[2][16 * 8192];
__device__ __align__(128) unsigned char g_img3[2][16 * 8192];
__device__ float g_c[3][BB * HH];
__device__ float g_hfin[2][BB * HH];
__device__ float g_h3[(TT + 1) * BB * HH];
__device__ float g_part[3 * 64 * 4096];
__device__ unsigned g_flag[3 * 64];

__device__ unsigned g_count = 0;
__device__ volatile unsigned g_gen = 0;

__device__ __forceinline__ u32 swz(u32 off) { return off ^ ((off >> 3) & 0x70); }

__device__ __forceinline__ u32 smem_u32(const void* p) {
    u32 r;
    asm("{ .reg .u64 t; cvta.to.shared.u64 t, %1; cvt.u32.u64 %0, t; }" : "=r"(r) : "l"(p));
    return r;
}
__device__ __forceinline__ void mbar_init(u32 a, u32 cnt) {
    asm volatile("mbarrier.init.shared.b64 [%0], %1;" :: "r"(a), "r"(cnt) : "memory");
}
__device__ __forceinline__ void mbar_expect_tx(u32 a, u32 bytes) {
    asm volatile("mbarrier.arrive.expect_tx.shared.b64 _, [%0], %1;" :: "r"(a), "r"(bytes) : "memory");
}
__device__ __forceinline__ void mbar_arrive(u32 a) {
    asm volatile("mbarrier.arrive.shared.b64 _, [%0];" :: "r"(a) : "memory");
}
__device__ __forceinline__ void mbar_wait(u32 a, u32 parity) {
    u32 done;
    asm volatile("{\n\t.reg .pred p;\n\t"
                 "mbarrier.try_wait.parity.acquire.cta.shared::cta.b64 p, [%1], %2;\n\t"
                 "selp.b32 %0, 1, 0, p;\n\t}"
                 : "=r"(done) : "r"(a), "r"(parity) : "memory");
    if (!done) {
        asm volatile("{\n\t.reg .pred P1;\n\t"
                     "W_%=:\n\t"
                     "mbarrier.try_wait.parity.acquire.cta.shared::cta.b64 P1, [%0], %1, 0x989680;\n\t"
                     "@P1 bra.uni D_%=;\n\t"
                     "bra.uni W_%=;\n\t"
                     "D_%=:\n\t}" :: "r"(a), "r"(parity) : "memory");
    }
}
__device__ __forceinline__ void bulk_g2s(u32 dst, const void* src, u32 bytes, u32 mbar) {
    asm volatile("cp.async.bulk.shared::cluster.global.mbarrier::complete_tx::bytes [%0], [%1], %2, [%3];"
                 :: "r"(dst), "l"(src), "r"(bytes), "r"(mbar) : "memory");
}

__device__ __forceinline__ void ldm4(u32 addr, u32* r) {
    asm volatile("ldmatrix.sync.aligned.m8n8.x4.shared.b16 {%0,%1,%2,%3}, [%4];"
                 : "=r"(r[0]), "=r"(r[1]), "=r"(r[2]), "=r"(r[3]) : "r"(addr));
}
__device__ __forceinline__ u32 ldm_addr(u32 tilebase, int rbase, int kq, int lane) {
    int row  = rbase + (lane & 7) + ((lane >> 3) & 1) * 8;
    int colb = kq * 32 + ((lane >> 4) & 1) * 16;
    return tilebase + swz((u32)(row * 128 + colb));
}
__device__ __forceinline__ void mma16816(float* d, const u32* a, u32 b0, u32 b1) {
    asm volatile("mma.sync.aligned.m16n8k16.row.col.f32.f16.f16.f32 "
                 "{%0,%1,%2,%3},{%4,%5,%6,%7},{%8,%9},{%0,%1,%2,%3};"
                 : "+f"(d[0]), "+f"(d[1]), "+f"(d[2]), "+f"(d[3])
                 : "r"(a[0]), "r"(a[1]), "r"(a[2]), "r"(a[3]), "r"(b0), "r"(b1));
}

// ---------------- grid barrier ----------------
__device__ __forceinline__ void gbar() {
    __syncthreads();
    if (threadIdx.x == 0) {
        unsigned gen = g_gen;
        __threadfence();
        unsigned a = atomicAdd(&g_count, 1);
        if (a == NBLK - 1) {
            atomicExch(&g_count, 0);
            __threadfence();
            g_gen = gen + 1;
        } else {
            while (g_gen == gen) { __nanosleep(32); }
            __threadfence();
        }
    }
    __syncthreads();
}

// ---------------- init ----------------
__global__ void init_zero() {
    int i = blockIdx.x * blockDim.x + threadIdx.x;
    if (i < BB * HH) {
        g_c[0][i] = 0.f; g_c[1][i] = 0.f; g_c[2][i] = 0.f;
        g_h3[i] = 0.f;
    }
    if (i < 3 * 64) g_flag[i] = 0u;
    int n32 = 16 * 8192 / 4;
    for (int j = i; j < n32; j += gridDim.x * blockDim.x) {
        ((u32*)g_img1[0])[j] = 0u;
        ((u32*)g_img2[0])[j] = 0u;
        ((u32*)g_img3[0])[j] = 0u;
    }
}

// ---------------- weight conversion (fp16, single) ----------------
__global__ void wconv(const float* __restrict__ W1, const float* __restrict__ W2,
                      const float* __restrict__ W3) {
    int l = blockIdx.y;
    size_t idx = (size_t)blockIdx.x * blockDim.x + threadIdx.x;
    int K = (l == 0) ? HH : 2 * HH;
    if (idx >= (size_t)K * GG) return;
    int k = (int)(idx >> 12);
    int n = (int)(idx & 4095);
    float w;
    if (l == 0)      w = W1[(size_t)(VV + k) * GG + n];
    else if (l == 1) w = W2[idx];
    else             w = W3[idx];
    __half hw = __float2half(w);
    int g = n >> 10, u = n & 1023;
    int nt = u >> 4, jj = u & 15;
    int nc = g * 16 + jj;
    int nch = K >> 6;
    size_t base = ((size_t)nt * nch + (k >> 6)) * 8192;
    u32 off = swz((u32)(nc * 128 + (k & 63) * 2));
    unsigned char* img = (l == 0) ? g_w0img : (l == 1) ? g_w1img : g_w2img;
    *(__half*)(img + base + off) = hw;
}

// ---------------- per-wave segment descriptors ----------------
struct Seg {
    const unsigned char* a;
    const unsigned char* wgt;
    int start;
    int nch;
    int l, t;
};

__device__ __forceinline__ void make_seg(Seg& s, int l, int t, int nt, int kh) {
    if (l == 0) {
        s.nch = 8;
        s.wgt = g_w0img + ((size_t)nt * 16 + (size_t)kh * 8) * 8192;
        s.a   = g_img1[t & 1] + (size_t)(kh * 8) * 8192;
    } else if (l == 1) {
        s.nch = 16;
        s.wgt = g_w1img + ((size_t)nt * 32 + (size_t)kh * 16) * 8192;
        s.a   = kh ? g_img2[t & 1] : g_img1[(t + 1) & 1];
    } else {
        s.nch = 16;
        s.wgt = g_w2img + ((size_t)nt * 32 + (size_t)kh * 16) * 8192;
        s.a   = kh ? g_img3[t & 1] : g_img2[(t + 1) & 1];
    }
    s.l = l; s.t = t;
}

// issue one chunk's bulk loads (tid0 only). Waits the stage's EMPTY barrier
// (all 16 warps arrived for the stage's previous occupant) before overwrite.
__device__ __forceinline__ void issue_chunk(u32 sb, u32 sbar, const Seg* segs, int ns,
                                            int g, u32 gg) {
    int s = 0;
    while (s < ns - 1 && g >= segs[s + 1].start) s++;
    int c = g - segs[s].start;
    const unsigned char* at = segs[s].a   + (size_t)c * 8192;
    const unsigned char* wt = segs[s].wgt + (size_t)c * 8192;
    u32 gc = gg + (u32)g;
    u32 st = gc & (NST - 1u);
    if (gc >= NST)
        mbar_wait(sbar + 64 + st * 8, ((gc >> 3) + 1u) & 1u);   // round (gc>>3)-1 complete
    u32 mb = sbar + st * 8;
    mbar_expect_tx(mb, 16384);
    bulk_g2s(sb + st * STG,         at, 8192, mb);
    bulk_g2s(sb + st * STG + 8192,  wt, 8192, mb);
}

// ---------------- persistent wavefront LSTM (decoupled-warp ring) ----------------
__global__ void __launch_bounds__(NTHR, 1) lstm_persist(
    const int*   __restrict__ X,
    const float* __restrict__ W1,
    const float* __restrict__ b1, const float* __restrict__ b2, const float* __restrict__ b3)
{
    extern __shared__ unsigned char dynsm[];
    u32 raw = smem_u32(dynsm);
    u32 sb = (raw + 127u) & ~127u;
    float* Sm = (float*)(dynsm + (sb - raw) + NST * STG);   // [64 c][65 m] = 16640B
    u32 sbar = sb + NST * STG + 16640;                      // full[8] @0, empty[8] @64

    const int tid  = threadIdx.x;
    const int wid  = tid >> 5;
    const int lane = tid & 31;
    const int bid  = blockIdx.x;
    const int nt   = bid >> 1;
    const int kh   = bid & 1;
    const int j0   = nt * 16;
    const int mt   = wid >> 2;        // 0..3
    const int nq   = wid & 3;         // 0..3
    const int m0   = mt * 16;
    const int nb   = nq * 16;

    if (tid == 0) {
#pragma unroll
        for (int s = 0; s < NST; s++) {
            mbar_init(sbar + s * 8, 1);         // full: TMA tx
            mbar_init(sbar + 64 + s * 8, 16);   // empty: one arrive per warp
        }
    }
    __syncthreads();

    u32 gg = 0;   // persistent chunk counter

    for (int w = 0; w < TT + 2; w++) {
        Seg segs[3];
        int ns = 0, total = 0;
#pragma unroll
        for (int l = 0; l < 3; l++) {
            int t = w - l;
            if (t >= 0 && t < TT) {
                make_seg(segs[ns], l, t, nt, kh);
                segs[ns].start = total;
                total += segs[ns].nch;
                ns++;
            }
        }

        // preload up to NST-1 stages (waits empty internally after first wave)
        if (tid == 0) {
#pragma unroll
            for (int i = 0; i < NST - 1; i++)
                if (i < total) issue_chunk(sb, sbar, segs, ns, i, gg);
        }

        int g = 0;
        for (int s = 0; s < ns; s++) {
            float acc[2][4];
#pragma unroll
            for (int i = 0; i < 2; i++)
#pragma unroll
                for (int q = 0; q < 4; q++) acc[i][q] = 0.f;

            const int nch = segs[s].nch;
            for (int c = 0; c < nch; c++) {
                u32 gc  = gg + (u32)g;
                u32 cur = gc & (NST - 1u);

                if (tid == 0 && g + NST - 1 < total)
                    issue_chunk(sb, sbar, segs, ns, g + NST - 1, gg);

                mbar_wait(sbar + cur * 8, (gc >> 3) & 1u);

                u32 At = sb + cur * STG;
                u32 Wt = At + 8192;
#pragma unroll
                for (int kq = 0; kq < 4; kq++) {
                    u32 a[4], b[4];
                    ldm4(ldm_addr(At, m0, kq, lane), a);
                    ldm4(ldm_addr(Wt, nb, kq, lane), b);
                    mma16816(acc[0], a, b[0], b[2]);
                    mma16816(acc[1], a, b[1], b[3]);
                }
                // MMAs consumed the ldmatrix regs -> smem reads complete; safe to release
                if (lane == 0) mbar_arrive(sbar + 64 + cur * 8);
                g++;
            }

            // ---- epilogue: K-half exchange + gates (3 sync points per wave) ----
            const int l = segs[s].l;
            const int t = segs[s].t;
            const int owner = (l == 1) ? 1 : 0;
            float* pbase = g_part + ((size_t)l * 64 + nt) * 4096;
            unsigned* flag = &g_flag[l * 64 + nt];

            if (kh != owner) {
                float4* pp4 = (float4*)pbase;
#pragma unroll
                for (int nti = 0; nti < 2; nti++) {
                    float4 v = make_float4(acc[nti][0], acc[nti][1], acc[nti][2], acc[nti][3]);
                    __stcg(&pp4[tid * 2 + nti], v);
                }
                __threadfence();
                __syncthreads();
                if (tid == 0) atomicExch(flag, (unsigned)(t + 1));
            } else {
                if (tid == 0) {
                    while (*(volatile unsigned*)flag != (unsigned)(t + 1)) __nanosleep(16);
                    __threadfence();
                }
                __syncthreads();
                const float4* pp4 = (const float4*)pbase;
#pragma unroll
                for (int nti = 0; nti < 2; nti++) {
                    float4 v = __ldcg(&pp4[tid * 2 + nti]);
                    acc[nti][0] += v.x; acc[nti][1] += v.y;
                    acc[nti][2] += v.z; acc[nti][3] += v.w;
                }
                {
                    int gid = lane >> 2, tig = lane & 3;
                    int mrow = m0 + gid;
#pragma unroll
                    for (int nti = 0; nti < 2; nti++) {
                        int cc = nb + nti * 8 + tig * 2;
                        Sm[cc * 65 + mrow]           = acc[nti][0];
                        Sm[(cc + 1) * 65 + mrow]     = acc[nti][1];
                        Sm[cc * 65 + mrow + 8]       = acc[nti][2];
                        Sm[(cc + 1) * 65 + mrow + 8] = acc[nti][3];
                    }
                }
                __syncthreads();

                const float* bias = (l == 0) ? b1 : (l == 1) ? b2 : b3;
                float* cbuf = g_c[l];
                unsigned char* imgout = (l == 0) ? g_img1[(t + 1) & 1]
                                      : (l == 1) ? g_img2[(t + 1) & 1]
                                                 : g_img3[(t + 1) & 1];
#pragma unroll
                for (int i = 0; i < 2; i++) {
                    int e  = tid + i * 512;
                    int m  = e & 63;
                    int jj = e >> 6;
                    int jg = j0 + jj;
                    float f  = Sm[jj * 65 + m]        + bias[jg];
                    float ig = Sm[(16 + jj) * 65 + m] + bias[HH + jg];
                    float og = Sm[(32 + jj) * 65 + m] + bias[2 * HH + jg];
                    float ct = Sm[(48 + jj) * 65 + m] + bias[3 * HH + jg];
                    if (l == 0) {
                        int xid = X[m * TT + t];
                        const float* wrow = W1 + (size_t)xid * GG + jg;
                        f  += wrow[0];
                        ig += wrow[HH];
                        og += wrow[2 * HH];
                        ct += wrow[3 * HH];
                    }
                    int cidx = m * HH + jg;
                    float cv = cbuf[cidx];
                    float sf = 1.f / (1.f + __expf(-f));
                    float si = 1.f / (1.f + __expf(-ig));
                    float so = 1.f / (1.f + __expf(-og));
                    float cn = sf * cv + si * tanhf(ct);
                    float hn = so * tanhf(cn);
                    cbuf[cidx] = cn;

                    __half hv = __float2half(hn);
                    unsigned char* cb = imgout + (size_t)(jg >> 6) * 8192;
                    u32 off = swz((u32)(m * 128 + (jg & 63) * 2));
                    *(__half*)(cb + off) = hv;

                    if (l == 2) g_h3[(size_t)(t + 1) * BB * HH + cidx] = hn;
                    else if (t == TT - 1) g_hfin[l][cidx] = hn;
                }
            }
        }
        gg += (u32)total;
        gbar();
    }
}

// ---------------- out GEMM (f32x2 SIMT) ----------------
__device__ __forceinline__ u64 ffma2(u64 a, u64 b, u64 c) {
    u64 d; asm("fma.rn.f32x2 %0, %1, %2, %3;" : "=l"(d) : "l"(a), "l"(b), "l"(c)); return d;
}
__device__ __forceinline__ u64 splat2(float w) {
    u64 d; asm("mov.b64 %0, {%1, %1};" : "=l"(d) : "f"(w)); return d;
}
__device__ __forceinline__ void unpack2(u64 v, float& lo, float& hi) {
    asm("mov.b64 {%0, %1}, %2;" : "=f"(lo), "=f"(hi) : "l"(v));
}

__global__ void __launch_bounds__(128) out_gemm(
    const float* __restrict__ Wout, const float* __restrict__ bout, float* __restrict__ out)
{
    const float* Amat = g_h3 + BB * HH;
    __shared__ __align__(16) float As[32][68];
    __shared__ __align__(16) float Ws[32][64];
    const int tid = threadIdx.x;
    const int n0 = blockIdx.x * 64;
    const int m0 = blockIdx.y * 64;
    const int tx = tid & 15;
    const int ty = tid >> 4;

    u64 acc[4][4];
#pragma unroll
    for (int pr = 0; pr < 4; pr++)
#pragma unroll
        for (int c = 0; c < 4; c++) acc[pr][c] = splat2(bout[n0 + tx * 4 + c]);

    for (int kc = 0; kc < HH; kc += 32) {
#pragma unroll
        for (int i = 0; i < 16; i++) {
            int idx = tid + i * 128;
            int r = idx >> 5, kk = idx & 31;
            As[kk][r] = Amat[(size_t)(m0 + r) * HH + kc + kk];
        }
#pragma unroll
        for (int i = 0; i < 16; i++) {
            int idx = tid + i * 128;
            int kk = idx >> 6, n = idx & 63;
            Ws[kk][n] = Wout[(size_t)(kc + kk) * VV + n0 + n];
        }
        __syncthreads();
#pragma unroll
        for (int kk = 0; kk < 32; kk++) {
            double2 xa = *(const double2*)&As[kk][ty * 8];
            double2 xb = *(const double2*)&As[kk][ty * 8 + 4];
            float4  wf = *(const float4*)&Ws[kk][tx * 4];
            u64 xp[4] = { __double_as_longlong(xa.x), __double_as_longlong(xa.y),
                          __double_as_longlong(xb.x), __double_as_longlong(xb.y) };
            u64 w0 = splat2(wf.x), w1 = splat2(wf.y), w2 = splat2(wf.z), w3 = splat2(wf.w);
#pragma unroll
            for (int pr = 0; pr < 4; pr++) {
                acc[pr][0] = ffma2(xp[pr], w0, acc[pr][0]);
                acc[pr][1] = ffma2(xp[pr], w1, acc[pr][1]);
                acc[pr][2] = ffma2(xp[pr], w2, acc[pr][2]);
                acc[pr][3] = ffma2(xp[pr], w3, acc[pr][3]);
            }
        }
        __syncthreads();
    }
#pragma unroll
    for (int pr = 0; pr < 4; pr++) {
        float lo[4], hi[4];
#pragma unroll
        for (int c = 0; c < 4; c++) unpack2(acc[pr][c], lo[c], hi[c]);
        int m = m0 + ty * 8 + pr * 2;
        *(float4*)&out[(size_t)m * VV + n0 + tx * 4]       = make_float4(lo[0], lo[1], lo[2], lo[3]);
        *(float4*)&out[(size_t)(m + 1) * VV + n0 + tx * 4] = make_float4(hi[0], hi[1], hi[2], hi[3]);
    }
}

__global__ void copy_states(float* __restrict__ out) {
    int i = blockIdx.x * blockDim.x + threadIdx.x;
    if (i < BB * HH) {
        out[0 * BB * HH + i] = g_hfin[0][i];
        out[1 * BB * HH + i] = g_c[0][i];
        out[2 * BB * HH + i] = g_hfin[1][i];
        out[3 * BB * HH + i] = g_c[1][i];
        out[4 * BB * HH + i] = g_h3[(size_t)TT * BB * HH + i];
        out[5 * BB * HH + i] = g_c[2][i];
    }
}

// ---------------- launch ----------------
extern "C" void kernel_launch(void* const* d_in, const int* in_sizes, int n_in,
                              void* d_out, int out_size) {
    const int*   X    = (const int*)  d_in[0];
    const float* W1   = (const float*)d_in[1];
    const float* b1   = (const float*)d_in[2];
    const float* W2   = (const float*)d_in[3];
    const float* b2   = (const float*)d_in[4];
    const float* W3   = (const float*)d_in[5];
    const float* b3   = (const float*)d_in[6];
    const float* Wout = (const float*)d_in[7];
    const float* bout = (const float*)d_in[8];
    float* out = (float*)d_out;
    (void)in_sizes; (void)n_in;

    static int attr_done = 0;
    if (!attr_done) {
        cudaFuncSetAttribute(lstm_persist, cudaFuncAttributeMaxDynamicSharedMemorySize, 148224);
        attr_done = 1;
    }

    init_zero<<<256, 256>>>();

    dim3 wgrid((2u * HH * GG + 255) / 256, 3);
    wconv<<<wgrid, 256>>>(W1, W2, W3);

    lstm_persist<<<NBLK, NTHR, 148224>>>(X, W1, b1, b2, b3);

    dim3 out_grid(VV / 64, (TT * BB) / 64);
    out_gemm<<<out_grid, 128>>>(Wout, bout, out);

    long long need = (long long)TT * BB * VV + 6LL * BB * HH;
    if ((long long)out_size >= need) {
        copy_states<<<(BB * HH + 255) / 256, 256>>>(out + (size_t)TT * BB * VV);
    }
}

// round 14
// speedup vs baseline: 1.2964x; 1.1051x over previous
#include <cuda_runtime.h>
#include <cuda_fp16.h>
#include <math.h>
#include <stdint.h>

#define BB 64
#define HH 1024
#define VV 2048
#define TT 256
#define GG 4096
#define NBLK 128
#define NTHR 512
#define STG 16384u   // stage stride: [A 8K][W 8K]
#define NST 8        // pipeline stages

typedef unsigned long long u64;
typedef unsigned int u32;

// ---------------- device globals ----------------
__device__ __align__(128) unsigned char g_w0img[8u * 1024 * 1024];
__device__ __align__(128) unsigned char g_w1img[16u * 1024 * 1024];
__device__ __align__(128) unsigned char g_w2img[16u * 1024 * 1024];
__device__ __align__(128) unsigned char g_img1[2][16 * 8192];
__device__ __align__(128) unsigned char g_img2[2][16 * 8192];
__device__ __align__(128) unsigned char g_img3[2][16 * 8192];
__device__ float g_c[3][BB * HH];
__device__ float g_hfin[2][BB * HH];
__device__ float g_h3[(TT + 1) * BB * HH];
__device__ float g_part[3 * 64 * 4096];
__device__ unsigned g_flag[3 * 64];

__device__ unsigned g_count = 0;
__device__ volatile unsigned g_gen = 0;

__device__ __forceinline__ u32 swz(u32 off) { return off ^ ((off >> 3) & 0x70); }

__device__ __forceinline__ u32 smem_u32(const void* p) {
    u32 r;
    asm("{ .reg .u64 t; cvta.to.shared.u64 t, %1; cvt.u32.u64 %0, t; }" : "=r"(r) : "l"(p));
    return r;
}
__device__ __forceinline__ void mbar_init(u32 a, u32 cnt) {
    asm volatile("mbarrier.init.shared.b64 [%0], %1;" :: "r"(a), "r"(cnt) : "memory");
}
__device__ __forceinline__ void mbar_expect_tx(u32 a, u32 bytes) {
    asm volatile("mbarrier.arrive.expect_tx.shared.b64 _, [%0], %1;" :: "r"(a), "r"(bytes) : "memory");
}
__device__ __forceinline__ void mbar_arrive(u32 a) {
    asm volatile("mbarrier.arrive.shared.b64 _, [%0];" :: "r"(a) : "memory");
}
__device__ __forceinline__ void mbar_wait(u32 a, u32 parity) {
    u32 done;
    asm volatile("{\n\t.reg .pred p;\n\t"
                 "mbarrier.try_wait.parity.acquire.cta.shared::cta.b64 p, [%1], %2;\n\t"
                 "selp.b32 %0, 1, 0, p;\n\t}"
                 : "=r"(done) : "r"(a), "r"(parity) : "memory");
    if (!done) {
        asm volatile("{\n\t.reg .pred P1;\n\t"
                     "W_%=:\n\t"
                     "mbarrier.try_wait.parity.acquire.cta.shared::cta.b64 P1, [%0], %1, 0x989680;\n\t"
                     "@P1 bra.uni D_%=;\n\t"
                     "bra.uni W_%=;\n\t"
                     "D_%=:\n\t}" :: "r"(a), "r"(parity) : "memory");
    }
}
__device__ __forceinline__ void bulk_g2s(u32 dst, const void* src, u32 bytes, u32 mbar) {
    asm volatile("cp.async.bulk.shared::cluster.global.mbarrier::complete_tx::bytes [%0], [%1], %2, [%3];"
                 :: "r"(dst), "l"(src), "r"(bytes), "r"(mbar) : "memory");
}

__device__ __forceinline__ void ldm4(u32 addr, u32* r) {
    asm volatile("ldmatrix.sync.aligned.m8n8.x4.shared.b16 {%0,%1,%2,%3}, [%4];"
                 : "=r"(r[0]), "=r"(r[1]), "=r"(r[2]), "=r"(r[3]) : "r"(addr));
}
__device__ __forceinline__ u32 ldm_addr(u32 tilebase, int rbase, int kq, int lane) {
    int row  = rbase + (lane & 7) + ((lane >> 3) & 1) * 8;
    int colb = kq * 32 + ((lane >> 4) & 1) * 16;
    return tilebase + swz((u32)(row * 128 + colb));
}
__device__ __forceinline__ void mma16816(float* d, const u32* a, u32 b0, u32 b1) {
    asm volatile("mma.sync.aligned.m16n8k16.row.col.f32.f16.f16.f32 "
                 "{%0,%1,%2,%3},{%4,%5,%6,%7},{%8,%9},{%0,%1,%2,%3};"
                 : "+f"(d[0]), "+f"(d[1]), "+f"(d[2]), "+f"(d[3])
                 : "r"(a[0]), "r"(a[1]), "r"(a[2]), "r"(a[3]), "r"(b0), "r"(b1));
}

// ---------------- grid barrier ----------------
__device__ __forceinline__ void gbar() {
    __syncthreads();
    if (threadIdx.x == 0) {
        unsigned gen = g_gen;
        __threadfence();
        unsigned a = atomicAdd(&g_count, 1);
        if (a == NBLK - 1) {
            atomicExch(&g_count, 0);
            __threadfence();
            g_gen = gen + 1;
        } else {
            while (g_gen == gen) { __nanosleep(32); }
            __threadfence();
        }
    }
    __syncthreads();
}

// ---------------- init ----------------
__global__ void init_zero() {
    int i = blockIdx.x * blockDim.x + threadIdx.x;
    if (i < BB * HH) {
        g_c[0][i] = 0.f; g_c[1][i] = 0.f; g_c[2][i] = 0.f;
        g_h3[i] = 0.f;
    }
    if (i < 3 * 64) g_flag[i] = 0u;
    int n32 = 16 * 8192 / 4;
    for (int j = i; j < n32; j += gridDim.x * blockDim.x) {
        ((u32*)g_img1[0])[j] = 0u;
        ((u32*)g_img2[0])[j] = 0u;
        ((u32*)g_img3[0])[j] = 0u;
    }
}

// ---------------- weight conversion (fp16, single) ----------------
__global__ void wconv(const float* __restrict__ W1, const float* __restrict__ W2,
                      const float* __restrict__ W3) {
    int l = blockIdx.y;
    size_t idx = (size_t)blockIdx.x * blockDim.x + threadIdx.x;
    int K = (l == 0) ? HH : 2 * HH;
    if (idx >= (size_t)K * GG) return;
    int k = (int)(idx >> 12);
    int n = (int)(idx & 4095);
    float w;
    if (l == 0)      w = W1[(size_t)(VV + k) * GG + n];
    else if (l == 1) w = W2[idx];
    else             w = W3[idx];
    __half hw = __float2half(w);
    int g = n >> 10, u = n & 1023;
    int nt = u >> 4, jj = u & 15;
    int nc = g * 16 + jj;
    int nch = K >> 6;
    size_t base = ((size_t)nt * nch + (k >> 6)) * 8192;
    u32 off = swz((u32)(nc * 128 + (k & 63) * 2));
    unsigned char* img = (l == 0) ? g_w0img : (l == 1) ? g_w1img : g_w2img;
    *(__half*)(img + base + off) = hw;
}

// ---------------- per-wave segment descriptors ----------------
struct Seg {
    const unsigned char* a;
    const unsigned char* wgt;
    int start;
    int nch;
    int l, t;
};

__device__ __forceinline__ void make_seg(Seg& s, int l, int t, int nt, int kh) {
    if (l == 0) {
        s.nch = 8;
        s.wgt = g_w0img + ((size_t)nt * 16 + (size_t)kh * 8) * 8192;
        s.a   = g_img1[t & 1] + (size_t)(kh * 8) * 8192;
    } else if (l == 1) {
        s.nch = 16;
        s.wgt = g_w1img + ((size_t)nt * 32 + (size_t)kh * 16) * 8192;
        s.a   = kh ? g_img2[t & 1] : g_img1[(t + 1) & 1];
    } else {
        s.nch = 16;
        s.wgt = g_w2img + ((size_t)nt * 32 + (size_t)kh * 16) * 8192;
        s.a   = kh ? g_img3[t & 1] : g_img2[(t + 1) & 1];
    }
    s.l = l; s.t = t;
}

// issue one chunk's bulk loads (tid0 only). Waits the stage's EMPTY barrier
// (all 16 warps arrived for the stage's previous occupant) before overwrite.
__device__ __forceinline__ void issue_chunk(u32 sb, u32 sbar, const Seg* segs, int ns,
                                            int g, u32 gg) {
    int s = 0;
    while (s < ns - 1 && g >= segs[s + 1].start) s++;
    int c = g - segs[s].start;
    const unsigned char* at = segs[s].a   + (size_t)c * 8192;
    const unsigned char* wt = segs[s].wgt + (size_t)c * 8192;
    u32 gc = gg + (u32)g;
    u32 st = gc & (NST - 1u);
    if (gc >= NST)
        mbar_wait(sbar + 64 + st * 8, ((gc >> 3) + 1u) & 1u);
    u32 mb = sbar + st * 8;
    mbar_expect_tx(mb, 16384);
    bulk_g2s(sb + st * STG,         at, 8192, mb);
    bulk_g2s(sb + st * STG + 8192,  wt, 8192, mb);
}

// ---------------- persistent wavefront LSTM (deferred-epilogue stream) ----------------
__global__ void __launch_bounds__(NTHR, 1) lstm_persist(
    const int*   __restrict__ X,
    const float* __restrict__ W1,
    const float* __restrict__ b1, const float* __restrict__ b2, const float* __restrict__ b3)
{
    extern __shared__ unsigned char dynsm[];
    u32 raw = smem_u32(dynsm);
    u32 sb = (raw + 127u) & ~127u;
    float* Sm = (float*)(dynsm + (sb - raw) + NST * STG);   // [64 c][65 m]
    u32 sbar = sb + NST * STG + 16640;                      // full[8] @0, empty[8] @64

    const int tid  = threadIdx.x;
    const int wid  = tid >> 5;
    const int lane = tid & 31;
    const int bid  = blockIdx.x;
    const int nt   = bid >> 1;
    const int kh   = bid & 1;
    const int j0   = nt * 16;
    const int mt   = wid >> 2;
    const int nq   = wid & 3;
    const int m0   = mt * 16;
    const int nb   = nq * 16;

    if (tid == 0) {
#pragma unroll
        for (int s = 0; s < NST; s++) {
            mbar_init(sbar + s * 8, 1);
            mbar_init(sbar + 64 + s * 8, 16);
        }
    }
    __syncthreads();

    u32 gg = 0;

    for (int w = 0; w < TT + 2; w++) {
        Seg segs[3];
        int ns = 0, total = 0;
#pragma unroll
        for (int l = 0; l < 3; l++) {
            int t = w - l;
            if (t >= 0 && t < TT) {
                make_seg(segs[ns], l, t, nt, kh);
                segs[ns].start = total;
                total += segs[ns].nch;
                ns++;
            }
        }

        if (tid == 0) {
#pragma unroll
            for (int i = 0; i < NST - 1; i++)
                if (i < total) issue_chunk(sb, sbar, segs, ns, i, gg);
        }

        // ---- uninterrupted MMA stream over all segments ----
        float acc[3][2][4];
#pragma unroll
        for (int s = 0; s < 3; s++)
#pragma unroll
            for (int i = 0; i < 2; i++)
#pragma unroll
                for (int q = 0; q < 4; q++) acc[s][i][q] = 0.f;

        int g = 0;
        for (int s = 0; s < ns; s++) {
            const int nch = segs[s].nch;
            for (int c = 0; c < nch; c++) {
                u32 gc  = gg + (u32)g;
                u32 cur = gc & (NST - 1u);

                if (tid == 0 && g + NST - 1 < total)
                    issue_chunk(sb, sbar, segs, ns, g + NST - 1, gg);

                mbar_wait(sbar + cur * 8, (gc >> 3) & 1u);

                u32 At = sb + cur * STG;
                u32 Wt = At + 8192;
#pragma unroll
                for (int kq = 0; kq < 4; kq++) {
                    u32 a[4], b[4];
                    ldm4(ldm_addr(At, m0, kq, lane), a);
                    ldm4(ldm_addr(Wt, nb, kq, lane), b);
                    mma16816(acc[s][0], a, b[0], b[2]);
                    mma16816(acc[s][1], a, b[1], b[3]);
                }
                if (lane == 0) mbar_arrive(sbar + 64 + cur * 8);
                g++;
            }

            // ---- inline non-blocking producer dump (no sync, no flag yet) ----
            const int owner = (segs[s].l == 1) ? 1 : 0;
            if (kh != owner) {
                float4* pp4 = (float4*)(g_part + ((size_t)segs[s].l * 64 + nt) * 4096);
#pragma unroll
                for (int nti = 0; nti < 2; nti++) {
                    float4 v = make_float4(acc[s][nti][0], acc[s][nti][1],
                                           acc[s][nti][2], acc[s][nti][3]);
                    __stcg(&pp4[tid * 2 + nti], v);
                }
            }
        }

        // ---- publish all produced flags at once ----
        __threadfence();
        __syncthreads();
        if (tid == 0) {
            for (int s = 0; s < ns; s++) {
                const int owner = (segs[s].l == 1) ? 1 : 0;
                if (kh != owner)
                    atomicExch(&g_flag[segs[s].l * 64 + nt], (unsigned)(segs[s].t + 1));
            }
        }

        // ---- owner epilogues in the wave tail ----
        for (int s = 0; s < ns; s++) {
            const int l = segs[s].l;
            const int t = segs[s].t;
            const int owner = (l == 1) ? 1 : 0;
            if (kh != owner) continue;

            unsigned* flag = &g_flag[l * 64 + nt];
            if (tid == 0) {
                while (*(volatile unsigned*)flag != (unsigned)(t + 1)) __nanosleep(16);
                __threadfence();
            }
            __syncthreads();

            const float4* pp4 = (const float4*)(g_part + ((size_t)l * 64 + nt) * 4096);
#pragma unroll
            for (int nti = 0; nti < 2; nti++) {
                float4 v = __ldcg(&pp4[tid * 2 + nti]);
                acc[s][nti][0] += v.x; acc[s][nti][1] += v.y;
                acc[s][nti][2] += v.z; acc[s][nti][3] += v.w;
            }
            {
                int gid = lane >> 2, tig = lane & 3;
                int mrow = m0 + gid;
#pragma unroll
                for (int nti = 0; nti < 2; nti++) {
                    int cc = nb + nti * 8 + tig * 2;
                    Sm[cc * 65 + mrow]           = acc[s][nti][0];
                    Sm[(cc + 1) * 65 + mrow]     = acc[s][nti][1];
                    Sm[cc * 65 + mrow + 8]       = acc[s][nti][2];
                    Sm[(cc + 1) * 65 + mrow + 8] = acc[s][nti][3];
                }
            }
            __syncthreads();

            const float* bias = (l == 0) ? b1 : (l == 1) ? b2 : b3;
            float* cbuf = g_c[l];
            unsigned char* imgout = (l == 0) ? g_img1[(t + 1) & 1]
                                  : (l == 1) ? g_img2[(t + 1) & 1]
                                             : g_img3[(t + 1) & 1];
#pragma unroll
            for (int i = 0; i < 2; i++) {
                int e  = tid + i * 512;
                int m  = e & 63;
                int jj = e >> 6;
                int jg = j0 + jj;
                float f  = Sm[jj * 65 + m]        + bias[jg];
                float ig = Sm[(16 + jj) * 65 + m] + bias[HH + jg];
                float og = Sm[(32 + jj) * 65 + m] + bias[2 * HH + jg];
                float ct = Sm[(48 + jj) * 65 + m] + bias[3 * HH + jg];
                if (l == 0) {
                    int xid = X[m * TT + t];
                    const float* wrow = W1 + (size_t)xid * GG + jg;
                    f  += wrow[0];
                    ig += wrow[HH];
                    og += wrow[2 * HH];
                    ct += wrow[3 * HH];
                }
                int cidx = m * HH + jg;
                float cv = cbuf[cidx];
                float sf = 1.f / (1.f + __expf(-f));
                float si = 1.f / (1.f + __expf(-ig));
                float so = 1.f / (1.f + __expf(-og));
                float cn = sf * cv + si * tanhf(ct);
                float hn = so * tanhf(cn);
                cbuf[cidx] = cn;

                __half hv = __float2half(hn);
                unsigned char* cb = imgout + (size_t)(jg >> 6) * 8192;
                u32 off = swz((u32)(m * 128 + (jg & 63) * 2));
                *(__half*)(cb + off) = hv;

                if (l == 2) g_h3[(size_t)(t + 1) * BB * HH + cidx] = hn;
                else if (t == TT - 1) g_hfin[l][cidx] = hn;
            }
            __syncthreads();   // Sm reuse guard for next owned segment
        }

        gg += (u32)total;
        gbar();
    }
}

// ---------------- out GEMM (f32x2 SIMT) ----------------
__device__ __forceinline__ u64 ffma2(u64 a, u64 b, u64 c) {
    u64 d; asm("fma.rn.f32x2 %0, %1, %2, %3;" : "=l"(d) : "l"(a), "l"(b), "l"(c)); return d;
}
__device__ __forceinline__ u64 splat2(float w) {
    u64 d; asm("mov.b64 %0, {%1, %1};" : "=l"(d) : "f"(w)); return d;
}
__device__ __forceinline__ void unpack2(u64 v, float& lo, float& hi) {
    asm("mov.b64 {%0, %1}, %2;" : "=f"(lo), "=f"(hi) : "l"(v));
}

__global__ void __launch_bounds__(128) out_gemm(
    const float* __restrict__ Wout, const float* __restrict__ bout, float* __restrict__ out)
{
    const float* Amat = g_h3 + BB * HH;
    __shared__ __align__(16) float As[32][68];
    __shared__ __align__(16) float Ws[32][64];
    const int tid = threadIdx.x;
    const int n0 = blockIdx.x * 64;
    const int m0 = blockIdx.y * 64;
    const int tx = tid & 15;
    const int ty = tid >> 4;

    u64 acc[4][4];
#pragma unroll
    for (int pr = 0; pr < 4; pr++)
#pragma unroll
        for (int c = 0; c < 4; c++) acc[pr][c] = splat2(bout[n0 + tx * 4 + c]);

    for (int kc = 0; kc < HH; kc += 32) {
#pragma unroll
        for (int i = 0; i < 16; i++) {
            int idx = tid + i * 128;
            int r = idx >> 5, kk = idx & 31;
            As[kk][r] = Amat[(size_t)(m0 + r) * HH + kc + kk];
        }
#pragma unroll
        for (int i = 0; i < 16; i++) {
            int idx = tid + i * 128;
            int kk = idx >> 6, n = idx & 63;
            Ws[kk][n] = Wout[(size_t)(kc + kk) * VV + n0 + n];
        }
        __syncthreads();
#pragma unroll
        for (int kk = 0; kk < 32; kk++) {
            double2 xa = *(const double2*)&As[kk][ty * 8];
            double2 xb = *(const double2*)&As[kk][ty * 8 + 4];
            float4  wf = *(const float4*)&Ws[kk][tx * 4];
            u64 xp[4] = { __double_as_longlong(xa.x), __double_as_longlong(xa.y),
                          __double_as_longlong(xb.x), __double_as_longlong(xb.y) };
            u64 w0 = splat2(wf.x), w1 = splat2(wf.y), w2 = splat2(wf.z), w3 = splat2(wf.w);
#pragma unroll
            for (int pr = 0; pr < 4; pr++) {
                acc[pr][0] = ffma2(xp[pr], w0, acc[pr][0]);
                acc[pr][1] = ffma2(xp[pr], w1, acc[pr][1]);
                acc[pr][2] = ffma2(xp[pr], w2, acc[pr][2]);
                acc[pr][3] = ffma2(xp[pr], w3, acc[pr][3]);
            }
        }
        __syncthreads();
    }
#pragma unroll
    for (int pr = 0; pr < 4; pr++) {
        float lo[4], hi[4];
#pragma unroll
        for (int c = 0; c < 4; c++) unpack2(acc[pr][c], lo[c], hi[c]);
        int m = m0 + ty * 8 + pr * 2;
        *(float4*)&out[(size_t)m * VV + n0 + tx * 4]       = make_float4(lo[0], lo[1], lo[2], lo[3]);
        *(float4*)&out[(size_t)(m + 1) * VV + n0 + tx * 4] = make_float4(hi[0], hi[1], hi[2], hi[3]);
    }
}

__global__ void copy_states(float* __restrict__ out) {
    int i = blockIdx.x * blockDim.x + threadIdx.x;
    if (i < BB * HH) {
        out[0 * BB * HH + i] = g_hfin[0][i];
        out[1 * BB * HH + i] = g_c[0][i];
        out[2 * BB * HH + i] = g_hfin[1][i];
        out[3 * BB * HH + i] = g_c[1][i];
        out[4 * BB * HH + i] = g_h3[(size_t)TT * BB * HH + i];
        out[5 * BB * HH + i] = g_c[2][i];
    }
}

// ---------------- launch ----------------
extern "C" void kernel_launch(void* const* d_in, const int* in_sizes, int n_in,
                              void* d_out, int out_size) {
    const int*   X    = (const int*)  d_in[0];
    const float* W1   = (const float*)d_in[1];
    const float* b1   = (const float*)d_in[2];
    const float* W2   = (const float*)d_in[3];
    const float* b2   = (const float*)d_in[4];
    const float* W3   = (const float*)d_in[5];
    const float* b3   = (const float*)d_in[6];
    const float* Wout = (const float*)d_in[7];
    const float* bout = (const float*)d_in[8];
    float* out = (float*)d_out;
    (void)in_sizes; (void)n_in;

    static int attr_done = 0;
    if (!attr_done) {
        cudaFuncSetAttribute(lstm_persist, cudaFuncAttributeMaxDynamicSharedMemorySize, 148224);
        attr_done = 1;
    }

    init_zero<<<256, 256>>>();

    dim3 wgrid((2u * HH * GG + 255) / 256, 3);
    wconv<<<wgrid, 256>>>(W1, W2, W3);

    lstm_persist<<<NBLK, NTHR, 148224>>>(X, W1, b1, b2, b3);

    dim3 out_grid(VV / 64, (TT * BB) / 64);
    out_gemm<<<out_grid, 128>>>(Wout, bout, out);

    long long need = (long long)TT * BB * VV + 6LL * BB * HH;
    if ((long long)out_size >= need) {
        copy_states<<<(BB * HH + 255) / 256, 256>>>(out + (size_t)TT * BB * VV);
    }
}

// round 16
// speedup vs baseline: 1.3255x; 1.0225x over previous
#include <cuda_runtime.h>
#include <cuda_fp16.h>
#include <math.h>
#include <stdint.h>

#define BB 64
#define HH 1024
#define VV 2048
#define TT 256
#define GG 4096
#define NBLK 128
#define NTHR 512
#define STG 16384u   // stage stride: [A 8K][W 8K]
#define NST 8        // pipeline stages

typedef unsigned long long u64;
typedef unsigned int u32;

// ---------------- device globals ----------------
__device__ __align__(128) unsigned char g_w0img[8u * 1024 * 1024];
__device__ __align__(128) unsigned char g_w1img[16u * 1024 * 1024];
__device__ __align__(128) unsigned char g_w2img[16u * 1024 * 1024];
__device__ __align__(128) unsigned char g_img1[2][16 * 8192];
__device__ __align__(128) unsigned char g_img2[2][16 * 8192];
__device__ __align__(128) unsigned char g_img3[2][16 * 8192];
__device__ float g_c[3][BB * HH];
__device__ float g_hfin[2][BB * HH];
__device__ float g_h3[(TT + 1) * BB * HH];
__device__ float g_part[3 * 64 * 4096];
__device__ unsigned g_flag[3 * 64];

__device__ unsigned g_count = 0;
__device__ volatile unsigned g_gen = 0;

__device__ __forceinline__ u32 swz(u32 off) { return off ^ ((off >> 3) & 0x70); }

__device__ __forceinline__ u32 smem_u32(const void* p) {
    u32 r;
    asm("{ .reg .u64 t; cvta.to.shared.u64 t, %1; cvt.u32.u64 %0, t; }" : "=r"(r) : "l"(p));
    return r;
}
__device__ __forceinline__ void mbar_init(u32 a, u32 cnt) {
    asm volatile("mbarrier.init.shared.b64 [%0], %1;" :: "r"(a), "r"(cnt) : "memory");
}
__device__ __forceinline__ void mbar_expect_tx(u32 a, u32 bytes) {
    asm volatile("mbarrier.arrive.expect_tx.shared.b64 _, [%0], %1;" :: "r"(a), "r"(bytes) : "memory");
}
__device__ __forceinline__ void mbar_arrive(u32 a) {
    asm volatile("mbarrier.arrive.shared.b64 _, [%0];" :: "r"(a) : "memory");
}
__device__ __forceinline__ void mbar_wait(u32 a, u32 parity) {
    u32 done;
    asm volatile("{\n\t.reg .pred p;\n\t"
                 "mbarrier.try_wait.parity.acquire.cta.shared::cta.b64 p, [%1], %2;\n\t"
                 "selp.b32 %0, 1, 0, p;\n\t}"
                 : "=r"(done) : "r"(a), "r"(parity) : "memory");
    if (!done) {
        asm volatile("{\n\t.reg .pred P1;\n\t"
                     "W_%=:\n\t"
                     "mbarrier.try_wait.parity.acquire.cta.shared::cta.b64 P1, [%0], %1, 0x989680;\n\t"
                     "@P1 bra.uni D_%=;\n\t"
                     "bra.uni W_%=;\n\t"
                     "D_%=:\n\t}" :: "r"(a), "r"(parity) : "memory");
    }
}
__device__ __forceinline__ void bulk_g2s(u32 dst, const void* src, u32 bytes, u32 mbar) {
    asm volatile("cp.async.bulk.shared::cluster.global.mbarrier::complete_tx::bytes [%0], [%1], %2, [%3];"
                 :: "r"(dst), "l"(src), "r"(bytes), "r"(mbar) : "memory");
}

__device__ __forceinline__ void ldm4(u32 addr, u32* r) {
    asm volatile("ldmatrix.sync.aligned.m8n8.x4.shared.b16 {%0,%1,%2,%3}, [%4];"
                 : "=r"(r[0]), "=r"(r[1]), "=r"(r[2]), "=r"(r[3]) : "r"(addr));
}
__device__ __forceinline__ u32 ldm_addr(u32 tilebase, int rbase, int kq, int lane) {
    int row  = rbase + (lane & 7) + ((lane >> 3) & 1) * 8;
    int colb = kq * 32 + ((lane >> 4) & 1) * 16;
    return tilebase + swz((u32)(row * 128 + colb));
}
__device__ __forceinline__ void mma16816(float* d, const u32* a, u32 b0, u32 b1) {
    asm volatile("mma.sync.aligned.m16n8k16.row.col.f32.f16.f16.f32 "
                 "{%0,%1,%2,%3},{%4,%5,%6,%7},{%8,%9},{%0,%1,%2,%3};"
                 : "+f"(d[0]), "+f"(d[1]), "+f"(d[2]), "+f"(d[3])
                 : "r"(a[0]), "r"(a[1]), "r"(a[2]), "r"(a[3]), "r"(b0), "r"(b1));
}

// ---------------- grid barrier ----------------
__device__ __forceinline__ void gbar() {
    __syncthreads();
    if (threadIdx.x == 0) {
        unsigned gen = g_gen;
        __threadfence();
        unsigned a = atomicAdd(&g_count, 1);
        if (a == NBLK - 1) {
            atomicExch(&g_count, 0);
            __threadfence();
            g_gen = gen + 1;
        } else {
            while (g_gen == gen) { __nanosleep(32); }
            __threadfence();
        }
    }
    __syncthreads();
}

// ---------------- init ----------------
__global__ void init_zero() {
    int i = blockIdx.x * blockDim.x + threadIdx.x;
    if (i < BB * HH) {
        g_c[0][i] = 0.f; g_c[1][i] = 0.f; g_c[2][i] = 0.f;
        g_h3[i] = 0.f;
    }
    if (i < 3 * 64) g_flag[i] = 0u;
    int n32 = 16 * 8192 / 4;
    for (int j = i; j < n32; j += gridDim.x * blockDim.x) {
        ((u32*)g_img1[0])[j] = 0u;
        ((u32*)g_img2[0])[j] = 0u;
        ((u32*)g_img3[0])[j] = 0u;
    }
}

// ---------------- weight conversion (fp16, single) ----------------
__global__ void wconv(const float* __restrict__ W1, const float* __restrict__ W2,
                      const float* __restrict__ W3) {
    int l = blockIdx.y;
    size_t idx = (size_t)blockIdx.x * blockDim.x + threadIdx.x;
    int K = (l == 0) ? HH : 2 * HH;
    if (idx >= (size_t)K * GG) return;
    int k = (int)(idx >> 12);
    int n = (int)(idx & 4095);
    float w;
    if (l == 0)      w = W1[(size_t)(VV + k) * GG + n];
    else if (l == 1) w = W2[idx];
    else             w = W3[idx];
    __half hw = __float2half(w);
    int g = n >> 10, u = n & 1023;
    int nt = u >> 4, jj = u & 15;
    int nc = g * 16 + jj;
    int nch = K >> 6;
    size_t base = ((size_t)nt * nch + (k >> 6)) * 8192;
    u32 off = swz((u32)(nc * 128 + (k & 63) * 2));
    unsigned char* img = (l == 0) ? g_w0img : (l == 1) ? g_w1img : g_w2img;
    *(__half*)(img + base + off) = hw;
}

// ---------------- per-wave segment descriptors ----------------
struct Seg {
    const unsigned char* a;
    const unsigned char* wgt;
    int start;
    int nch;
    int l, t;
};

__device__ __forceinline__ void make_seg(Seg& s, int l, int t, int nt, int kh) {
    if (l == 0) {
        s.nch = 8;
        s.wgt = g_w0img + ((size_t)nt * 16 + (size_t)kh * 8) * 8192;
        s.a   = g_img1[t & 1] + (size_t)(kh * 8) * 8192;
    } else if (l == 1) {
        s.nch = 16;
        s.wgt = g_w1img + ((size_t)nt * 32 + (size_t)kh * 16) * 8192;
        s.a   = kh ? g_img2[t & 1] : g_img1[(t + 1) & 1];
    } else {
        s.nch = 16;
        s.wgt = g_w2img + ((size_t)nt * 32 + (size_t)kh * 16) * 8192;
        s.a   = kh ? g_img3[t & 1] : g_img2[(t + 1) & 1];
    }
    s.l = l; s.t = t;
}

// issue one chunk's bulk loads (tid0 only); waits stage's EMPTY barrier before overwrite.
// Only ever called with prefetch distance NST-1, so the empty wait targets the
// PREVIOUS chunk's stage (already released by this warp; others progress freely).
__device__ __forceinline__ void issue_chunk(u32 sb, u32 sbar, const Seg* segs, int ns,
                                            int g, u32 gg) {
    int s = 0;
    while (s < ns - 1 && g >= segs[s + 1].start) s++;
    int c = g - segs[s].start;
    const unsigned char* at = segs[s].a   + (size_t)c * 8192;
    const unsigned char* wt = segs[s].wgt + (size_t)c * 8192;
    u32 gc = gg + (u32)g;
    u32 st = gc & (NST - 1u);
    if (gc >= NST)
        mbar_wait(sbar + 64 + st * 8, ((gc >> 3) + 1u) & 1u);
    u32 mb = sbar + st * 8;
    mbar_expect_tx(mb, 16384);
    bulk_g2s(sb + st * STG,         at, 8192, mb);
    bulk_g2s(sb + st * STG + 8192,  wt, 8192, mb);
}

// ---------------- persistent wavefront LSTM (register-pipelined fragments) ----------------
__global__ void __launch_bounds__(NTHR, 1) lstm_persist(
    const int*   __restrict__ X,
    const float* __restrict__ W1,
    const float* __restrict__ b1, const float* __restrict__ b2, const float* __restrict__ b3)
{
    extern __shared__ unsigned char dynsm[];
    u32 raw = smem_u32(dynsm);
    u32 sb = (raw + 127u) & ~127u;
    float* Sm = (float*)(dynsm + (sb - raw) + NST * STG);
    u32 sbar = sb + NST * STG + 16640;   // full[8] @0, empty[8] @64

    const int tid  = threadIdx.x;
    const int wid  = tid >> 5;
    const int lane = tid & 31;
    const int bid  = blockIdx.x;
    const int nt   = bid >> 1;
    const int kh   = bid & 1;
    const int j0   = nt * 16;
    const int mt   = wid >> 2;
    const int nq   = wid & 3;
    const int m0   = mt * 16;
    const int nb   = nq * 16;

    if (tid == 0) {
#pragma unroll
        for (int s = 0; s < NST; s++) {
            mbar_init(sbar + s * 8, 1);
            mbar_init(sbar + 64 + s * 8, 16);
        }
    }
    __syncthreads();

    u32 gg = 0;

    for (int w = 0; w < TT + 2; w++) {
        Seg segs[3];
        int ns = 0, total = 0;
#pragma unroll
        for (int l = 0; l < 3; l++) {
            int t = w - l;
            if (t >= 0 && t < TT) {
                make_seg(segs[ns], l, t, nt, kh);
                segs[ns].start = total;
                total += segs[ns].nch;
                ns++;
            }
        }

        // preload stages 0..NST-2
        if (tid == 0) {
#pragma unroll
            for (int i = 0; i < NST - 1; i++)
                if (i < total) issue_chunk(sb, sbar, segs, ns, i, gg);
        }

        float acc[3][2][4];
#pragma unroll
        for (int s = 0; s < 3; s++)
#pragma unroll
            for (int i = 0; i < 2; i++)
#pragma unroll
                for (int q = 0; q < 4; q++) acc[s][i][q] = 0.f;

        int g = 0;
        for (int s = 0; s < ns; s++) {
            const int nch = segs[s].nch;

            // ---- segment prologue: wait first chunk's full, preload kq0 frags ----
            u32 af[2][4], bf[2][4];
            {
                u32 gc = gg + (u32)g;
                u32 cur = gc & (NST - 1u);
                mbar_wait(sbar + cur * 8, (gc >> 3) & 1u);
                u32 At = sb + cur * STG;
                ldm4(ldm_addr(At, m0, 0, lane), af[0]);
                ldm4(ldm_addr(At + 8192, nb, 0, lane), bf[0]);
            }

            int p = 0;
            for (int c = 0; c < nch; c++) {
                u32 gc  = gg + (u32)g;
                u32 cur = gc & (NST - 1u);

                // producer: issue chunk g+NST-1 (stage (gc-1)&7 — previous chunk's
                // stage, released by this warp last iteration; deadlock-free)
                if (tid == 0 && g + NST - 1 < total)
                    issue_chunk(sb, sbar, segs, ns, g + NST - 1, gg);

#pragma unroll
                for (int kq = 0; kq < 4; kq++) {
                    if (kq < 3) {
                        u32 At = sb + cur * STG;
                        ldm4(ldm_addr(At, m0, kq + 1, lane), af[p ^ 1]);
                        ldm4(ldm_addr(At + 8192, nb, kq + 1, lane), bf[p ^ 1]);
                    } else if (c + 1 < nch) {
                        u32 gn  = gc + 1;
                        u32 nxt = gn & (NST - 1u);
                        mbar_wait(sbar + nxt * 8, (gn >> 3) & 1u);
                        u32 At = sb + nxt * STG;
                        ldm4(ldm_addr(At, m0, 0, lane), af[p ^ 1]);
                        ldm4(ldm_addr(At + 8192, nb, 0, lane), bf[p ^ 1]);
                    }
                    mma16816(acc[s][0], af[p], bf[p][0], bf[p][2]);
                    mma16816(acc[s][1], af[p], bf[p][1], bf[p][3]);
                    if (kq == 3 && lane == 0) mbar_arrive(sbar + 64 + cur * 8);
                    p ^= 1;
                }
                g++;
            }

            // ---- inline non-blocking producer dump ----
            const int owner = (segs[s].l == 1) ? 1 : 0;
            if (kh != owner) {
                float4* pp4 = (float4*)(g_part + ((size_t)segs[s].l * 64 + nt) * 4096);
#pragma unroll
                for (int nti = 0; nti < 2; nti++) {
                    float4 v = make_float4(acc[s][nti][0], acc[s][nti][1],
                                           acc[s][nti][2], acc[s][nti][3]);
                    __stcg(&pp4[tid * 2 + nti], v);
                }
            }
        }

        // ---- publish flags ----
        __threadfence();
        __syncthreads();
        if (tid == 0) {
            for (int s = 0; s < ns; s++) {
                const int owner = (segs[s].l == 1) ? 1 : 0;
                if (kh != owner)
                    atomicExch(&g_flag[segs[s].l * 64 + nt], (unsigned)(segs[s].t + 1));
            }
        }

        // ---- owner epilogues in the wave tail ----
        for (int s = 0; s < ns; s++) {
            const int l = segs[s].l;
            const int t = segs[s].t;
            const int owner = (l == 1) ? 1 : 0;
            if (kh != owner) continue;

            unsigned* flag = &g_flag[l * 64 + nt];
            if (tid == 0) {
                while (*(volatile unsigned*)flag != (unsigned)(t + 1)) __nanosleep(16);
                __threadfence();
            }
            __syncthreads();

            const float4* pp4 = (const float4*)(g_part + ((size_t)l * 64 + nt) * 4096);
#pragma unroll
            for (int nti = 0; nti < 2; nti++) {
                float4 v = __ldcg(&pp4[tid * 2 + nti]);
                acc[s][nti][0] += v.x; acc[s][nti][1] += v.y;
                acc[s][nti][2] += v.z; acc[s][nti][3] += v.w;
            }
            {
                int gid = lane >> 2, tig = lane & 3;
                int mrow = m0 + gid;
#pragma unroll
                for (int nti = 0; nti < 2; nti++) {
                    int cc = nb + nti * 8 + tig * 2;
                    Sm[cc * 65 + mrow]           = acc[s][nti][0];
                    Sm[(cc + 1) * 65 + mrow]     = acc[s][nti][1];
                    Sm[cc * 65 + mrow + 8]       = acc[s][nti][2];
                    Sm[(cc + 1) * 65 + mrow + 8] = acc[s][nti][3];
                }
            }
            __syncthreads();

            const float* bias = (l == 0) ? b1 : (l == 1) ? b2 : b3;
            float* cbuf = g_c[l];
            unsigned char* imgout = (l == 0) ? g_img1[(t + 1) & 1]
                                  : (l == 1) ? g_img2[(t + 1) & 1]
                                             : g_img3[(t + 1) & 1];
#pragma unroll
            for (int i = 0; i < 2; i++) {
                int e  = tid + i * 512;
                int m  = e & 63;
                int jj = e >> 6;
                int jg = j0 + jj;
                float f  = Sm[jj * 65 + m]        + bias[jg];
                float ig = Sm[(16 + jj) * 65 + m] + bias[HH + jg];
                float og = Sm[(32 + jj) * 65 + m] + bias[2 * HH + jg];
                float ct = Sm[(48 + jj) * 65 + m] + bias[3 * HH + jg];
                if (l == 0) {
                    int xid = X[m * TT + t];
                    const float* wrow = W1 + (size_t)xid * GG + jg;
                    f  += wrow[0];
                    ig += wrow[HH];
                    og += wrow[2 * HH];
                    ct += wrow[3 * HH];
                }
                int cidx = m * HH + jg;
                float cv = cbuf[cidx];
                float sf = 1.f / (1.f + __expf(-f));
                float si = 1.f / (1.f + __expf(-ig));
                float so = 1.f / (1.f + __expf(-og));
                float cn = sf * cv + si * tanhf(ct);
                float hn = so * tanhf(cn);
                cbuf[cidx] = cn;

                __half hv = __float2half(hn);
                unsigned char* cb = imgout + (size_t)(jg >> 6) * 8192;
                u32 off = swz((u32)(m * 128 + (jg & 63) * 2));
                *(__half*)(cb + off) = hv;

                if (l == 2) g_h3[(size_t)(t + 1) * BB * HH + cidx] = hn;
                else if (t == TT - 1) g_hfin[l][cidx] = hn;
            }
            __syncthreads();
        }

        gg += (u32)total;
        gbar();
    }
}

// ---------------- out GEMM (f32x2 SIMT) ----------------
__device__ __forceinline__ u64 ffma2(u64 a, u64 b, u64 c) {
    u64 d; asm("fma.rn.f32x2 %0, %1, %2, %3;" : "=l"(d) : "l"(a), "l"(b), "l"(c)); return d;
}
__device__ __forceinline__ u64 splat2(float w) {
    u64 d; asm("mov.b64 %0, {%1, %1};" : "=l"(d) : "f"(w)); return d;
}
__device__ __forceinline__ void unpack2(u64 v, float& lo, float& hi) {
    asm("mov.b64 {%0, %1}, %2;" : "=f"(lo), "=f"(hi) : "l"(v));
}

__global__ void __launch_bounds__(128) out_gemm(
    const float* __restrict__ Wout, const float* __restrict__ bout, float* __restrict__ out)
{
    const float* Amat = g_h3 + BB * HH;
    __shared__ __align__(16) float As[32][68];
    __shared__ __align__(16) float Ws[32][64];
    const int tid = threadIdx.x;
    const int n0 = blockIdx.x * 64;
    const int m0 = blockIdx.y * 64;
    const int tx = tid & 15;
    const int ty = tid >> 4;

    u64 acc[4][4];
#pragma unroll
    for (int pr = 0; pr < 4; pr++)
#pragma unroll
        for (int c = 0; c < 4; c++) acc[pr][c] = splat2(bout[n0 + tx * 4 + c]);

    for (int kc = 0; kc < HH; kc += 32) {
#pragma unroll
        for (int i = 0; i < 16; i++) {
            int idx = tid + i * 128;
            int r = idx >> 5, kk = idx & 31;
            As[kk][r] = Amat[(size_t)(m0 + r) * HH + kc + kk];
        }
#pragma unroll
        for (int i = 0; i < 16; i++) {
            int idx = tid + i * 128;
            int kk = idx >> 6, n = idx & 63;
            Ws[kk][n] = Wout[(size_t)(kc + kk) * VV + n0 + n];
        }
        __syncthreads();
#pragma unroll
        for (int kk = 0; kk < 32; kk++) {
            double2 xa = *(const double2*)&As[kk][ty * 8];
            double2 xb = *(const double2*)&As[kk][ty * 8 + 4];
            float4  wf = *(const float4*)&Ws[kk][tx * 4];
            u64 xp[4] = { __double_as_longlong(xa.x), __double_as_longlong(xa.y),
                          __double_as_longlong(xb.x), __double_as_longlong(xb.y) };
            u64 w0 = splat2(wf.x), w1 = splat2(wf.y), w2 = splat2(wf.z), w3 = splat2(wf.w);
#pragma unroll
            for (int pr = 0; pr < 4; pr++) {
                acc[pr][0] = ffma2(xp[pr], w0, acc[pr][0]);
                acc[pr][1] = ffma2(xp[pr], w1, acc[pr][1]);
                acc[pr][2] = ffma2(xp[pr], w2, acc[pr][2]);
                acc[pr][3] = ffma2(xp[pr], w3, acc[pr][3]);
            }
        }
        __syncthreads();
    }
#pragma unroll
    for (int pr = 0; pr < 4; pr++) {
        float lo[4], hi[4];
#pragma unroll
        for (int c = 0; c < 4; c++) unpack2(acc[pr][c], lo[c], hi[c]);
        int m = m0 + ty * 8 + pr * 2;
        *(float4*)&out[(size_t)m * VV + n0 + tx * 4]       = make_float4(lo[0], lo[1], lo[2], lo[3]);
        *(float4*)&out[(size_t)(m + 1) * VV + n0 + tx * 4] = make_float4(hi[0], hi[1], hi[2], hi[3]);
    }
}

__global__ void copy_states(float* __restrict__ out) {
    int i = blockIdx.x * blockDim.x + threadIdx.x;
    if (i < BB * HH) {
        out[0 * BB * HH + i] = g_hfin[0][i];
        out[1 * BB * HH + i] = g_c[0][i];
        out[2 * BB * HH + i] = g_hfin[1][i];
        out[3 * BB * HH + i] = g_c[1][i];
        out[4 * BB * HH + i] = g_h3[(size_t)TT * BB * HH + i];
        out[5 * BB * HH + i] = g_c[2][i];
    }
}

// ---------------- launch ----------------
extern "C" void kernel_launch(void* const* d_in, const int* in_sizes, int n_in,
                              void* d_out, int out_size) {
    const int*   X    = (const int*)  d_in[0];
    const float* W1   = (const float*)d_in[1];
    const float* b1   = (const float*)d_in[2];
    const float* W2   = (const float*)d_in[3];
    const float* b2   = (const float*)d_in[4];
    const float* W3   = (const float*)d_in[5];
    const float* b3   = (const float*)d_in[6];
    const float* Wout = (const float*)d_in[7];
    const float* bout = (const float*)d_in[8];
    float* out = (float*)d_out;
    (void)in_sizes; (void)n_in;

    static int attr_done = 0;
    if (!attr_done) {
        cudaFuncSetAttribute(lstm_persist, cudaFuncAttributeMaxDynamicSharedMemorySize, 148224);
        attr_done = 1;
    }

    init_zero<<<256, 256>>>();

    dim3 wgrid((2u * HH * GG + 255) / 256, 3);
    wconv<<<wgrid, 256>>>(W1, W2, W3);

    lstm_persist<<<NBLK, NTHR, 148224>>>(X, W1, b1, b2, b3);

    dim3 out_grid(VV / 64, (TT * BB) / 64);
    out_gemm<<<out_grid, 128>>>(Wout, bout, out);

    long long need = (long long)TT * BB * VV + 6LL * BB * HH;
    if ((long long)out_size >= need) {
        copy_states<<<(BB * HH + 255) / 256, 256>>>(out + (size_t)TT * BB * VV);
    }
}

// round 17
// speedup vs baseline: 1.4435x; 1.0890x over previous
#include <cuda_runtime.h>
#include <cuda_fp16.h>
#include <math.h>
#include <stdint.h>

#define BB 64
#define HH 1024
#define VV 2048
#define TT 256
#define GG 4096
#define NBLK 128
#define NTHR 512
#define STG 16384u   // stage stride: [A 8K][W 8K]
#define NST 8        // pipeline stages

typedef unsigned long long u64;
typedef unsigned int u32;

// ---------------- device globals ----------------
__device__ __align__(128) unsigned char g_w0img[8u * 1024 * 1024];
__device__ __align__(128) unsigned char g_w1img[16u * 1024 * 1024];
__device__ __align__(128) unsigned char g_w2img[16u * 1024 * 1024];
__device__ __align__(128) unsigned char g_woimg[4u * 1024 * 1024];      // Wout fp16 tiles
__device__ __align__(128) unsigned char g_h3img[32u * 1024 * 1024];     // h3 history fp16 tiles
__device__ __align__(128) unsigned char g_img1[2][16 * 8192];
__device__ __align__(128) unsigned char g_img2[2][16 * 8192];
__device__ __align__(128) unsigned char g_img3[2][16 * 8192];
__device__ float g_c[3][BB * HH];
__device__ float g_hfin[2][BB * HH];
__device__ float g_hfin3[BB * HH];
__device__ float g_part[3 * 64 * 4096];
__device__ unsigned g_flag[3 * 64];

__device__ unsigned g_count = 0;
__device__ volatile unsigned g_gen = 0;

__device__ __forceinline__ u32 swz(u32 off) { return off ^ ((off >> 3) & 0x70); }

__device__ __forceinline__ u32 smem_u32(const void* p) {
    u32 r;
    asm("{ .reg .u64 t; cvta.to.shared.u64 t, %1; cvt.u32.u64 %0, t; }" : "=r"(r) : "l"(p));
    return r;
}
__device__ __forceinline__ void mbar_init(u32 a, u32 cnt) {
    asm volatile("mbarrier.init.shared.b64 [%0], %1;" :: "r"(a), "r"(cnt) : "memory");
}
__device__ __forceinline__ void mbar_expect_tx(u32 a, u32 bytes) {
    asm volatile("mbarrier.arrive.expect_tx.shared.b64 _, [%0], %1;" :: "r"(a), "r"(bytes) : "memory");
}
__device__ __forceinline__ void mbar_arrive(u32 a) {
    asm volatile("mbarrier.arrive.shared.b64 _, [%0];" :: "r"(a) : "memory");
}
__device__ __forceinline__ void mbar_wait(u32 a, u32 parity) {
    u32 done;
    asm volatile("{\n\t.reg .pred p;\n\t"
                 "mbarrier.try_wait.parity.acquire.cta.shared::cta.b64 p, [%1], %2;\n\t"
                 "selp.b32 %0, 1, 0, p;\n\t}"
                 : "=r"(done) : "r"(a), "r"(parity) : "memory");
    if (!done) {
        asm volatile("{\n\t.reg .pred P1;\n\t"
                     "W_%=:\n\t"
                     "mbarrier.try_wait.parity.acquire.cta.shared::cta.b64 P1, [%0], %1, 0x989680;\n\t"
                     "@P1 bra.uni D_%=;\n\t"
                     "bra.uni W_%=;\n\t"
                     "D_%=:\n\t}" :: "r"(a), "r"(parity) : "memory");
    }
}
__device__ __forceinline__ void bulk_g2s(u32 dst, const void* src, u32 bytes, u32 mbar) {
    asm volatile("cp.async.bulk.shared::cluster.global.mbarrier::complete_tx::bytes [%0], [%1], %2, [%3];"
                 :: "r"(dst), "l"(src), "r"(bytes), "r"(mbar) : "memory");
}
__device__ __forceinline__ void cp16(u32 d, const void* s) {
    asm volatile("cp.async.cg.shared.global [%0], [%1], 16;" :: "r"(d), "l"(s) : "memory");
}
__device__ __forceinline__ void cp_commit() { asm volatile("cp.async.commit_group;" ::: "memory"); }
__device__ __forceinline__ void cp_wait1()  { asm volatile("cp.async.wait_group 1;" ::: "memory"); }
__device__ __forceinline__ void cp_wait0()  { asm volatile("cp.async.wait_group 0;" ::: "memory"); }

__device__ __forceinline__ void ldm4(u32 addr, u32* r) {
    asm volatile("ldmatrix.sync.aligned.m8n8.x4.shared.b16 {%0,%1,%2,%3}, [%4];"
                 : "=r"(r[0]), "=r"(r[1]), "=r"(r[2]), "=r"(r[3]) : "r"(addr));
}
__device__ __forceinline__ u32 ldm_addr(u32 tilebase, int rbase, int kq, int lane) {
    int row  = rbase + (lane & 7) + ((lane >> 3) & 1) * 8;
    int colb = kq * 32 + ((lane >> 4) & 1) * 16;
    return tilebase + swz((u32)(row * 128 + colb));
}
__device__ __forceinline__ void mma16816(float* d, const u32* a, u32 b0, u32 b1) {
    asm volatile("mma.sync.aligned.m16n8k16.row.col.f32.f16.f16.f32 "
                 "{%0,%1,%2,%3},{%4,%5,%6,%7},{%8,%9},{%0,%1,%2,%3};"
                 : "+f"(d[0]), "+f"(d[1]), "+f"(d[2]), "+f"(d[3])
                 : "r"(a[0]), "r"(a[1]), "r"(a[2]), "r"(a[3]), "r"(b0), "r"(b1));
}

// ---------------- grid barrier ----------------
__device__ __forceinline__ void gbar() {
    __syncthreads();
    if (threadIdx.x == 0) {
        unsigned gen = g_gen;
        __threadfence();
        unsigned a = atomicAdd(&g_count, 1);
        if (a == NBLK - 1) {
            atomicExch(&g_count, 0);
            __threadfence();
            g_gen = gen + 1;
        } else {
            while (g_gen == gen) { __nanosleep(32); }
            __threadfence();
        }
    }
    __syncthreads();
}

// ---------------- init ----------------
__global__ void init_zero() {
    int i = blockIdx.x * blockDim.x + threadIdx.x;
    if (i < BB * HH) {
        g_c[0][i] = 0.f; g_c[1][i] = 0.f; g_c[2][i] = 0.f;
    }
    if (i < 3 * 64) g_flag[i] = 0u;
    int n32 = 16 * 8192 / 4;
    for (int j = i; j < n32; j += gridDim.x * blockDim.x) {
        ((u32*)g_img1[0])[j] = 0u;
        ((u32*)g_img2[0])[j] = 0u;
        ((u32*)g_img3[0])[j] = 0u;
    }
}

// ---------------- weight conversion (fp16 images; l=3 converts Wout) ----------------
__global__ void wconv(const float* __restrict__ W1, const float* __restrict__ W2,
                      const float* __restrict__ W3, const float* __restrict__ Wout) {
    int l = blockIdx.y;
    size_t idx = (size_t)blockIdx.x * blockDim.x + threadIdx.x;
    if (l == 3) {
        if (idx >= (size_t)HH * VV) return;
        int k = (int)(idx >> 11);          // 0..1023
        int n = (int)(idx & 2047);         // 0..2047
        __half hw = __float2half(Wout[idx]);
        size_t base = ((size_t)(n >> 6) * 16 + (size_t)(k >> 6)) * 8192;
        u32 off = swz((u32)((n & 63) * 128 + (k & 63) * 2));
        *(__half*)(g_woimg + base + off) = hw;
        return;
    }
    int K = (l == 0) ? HH : 2 * HH;
    if (idx >= (size_t)K * GG) return;
    int k = (int)(idx >> 12);
    int n = (int)(idx & 4095);
    float w;
    if (l == 0)      w = W1[(size_t)(VV + k) * GG + n];
    else if (l == 1) w = W2[idx];
    else             w = W3[idx];
    __half hw = __float2half(w);
    int g = n >> 10, u = n & 1023;
    int nt = u >> 4, jj = u & 15;
    int nc = g * 16 + jj;
    int nch = K >> 6;
    size_t base = ((size_t)nt * nch + (k >> 6)) * 8192;
    u32 off = swz((u32)(nc * 128 + (k & 63) * 2));
    unsigned char* img = (l == 0) ? g_w0img : (l == 1) ? g_w1img : g_w2img;
    *(__half*)(img + base + off) = hw;
}

// ---------------- per-wave segment descriptors ----------------
struct Seg {
    const unsigned char* a;
    const unsigned char* wgt;
    int start;
    int nch;
    int l, t;
};

__device__ __forceinline__ void make_seg(Seg& s, int l, int t, int nt, int kh) {
    if (l == 0) {
        s.nch = 8;
        s.wgt = g_w0img + ((size_t)nt * 16 + (size_t)kh * 8) * 8192;
        s.a   = g_img1[t & 1] + (size_t)(kh * 8) * 8192;
    } else if (l == 1) {
        s.nch = 16;
        s.wgt = g_w1img + ((size_t)nt * 32 + (size_t)kh * 16) * 8192;
        s.a   = kh ? g_img2[t & 1] : g_img1[(t + 1) & 1];
    } else {
        s.nch = 16;
        s.wgt = g_w2img + ((size_t)nt * 32 + (size_t)kh * 16) * 8192;
        s.a   = kh ? g_img3[t & 1] : g_img2[(t + 1) & 1];
    }
    s.l = l; s.t = t;
}

// issue one chunk's bulk loads (tid0 only); prefetch distance NST-1 => deadlock-free
__device__ __forceinline__ void issue_chunk(u32 sb, u32 sbar, const Seg* segs, int ns,
                                            int g, u32 gg) {
    int s = 0;
    while (s < ns - 1 && g >= segs[s + 1].start) s++;
    int c = g - segs[s].start;
    const unsigned char* at = segs[s].a   + (size_t)c * 8192;
    const unsigned char* wt = segs[s].wgt + (size_t)c * 8192;
    u32 gc = gg + (u32)g;
    u32 st = gc & (NST - 1u);
    if (gc >= NST)
        mbar_wait(sbar + 64 + st * 8, ((gc >> 3) + 1u) & 1u);
    u32 mb = sbar + st * 8;
    mbar_expect_tx(mb, 16384);
    bulk_g2s(sb + st * STG,         at, 8192, mb);
    bulk_g2s(sb + st * STG + 8192,  wt, 8192, mb);
}

// ---------------- persistent wavefront LSTM ----------------
__global__ void __launch_bounds__(NTHR, 1) lstm_persist(
    const int*   __restrict__ X,
    const float* __restrict__ W1,
    const float* __restrict__ b1, const float* __restrict__ b2, const float* __restrict__ b3)
{
    extern __shared__ unsigned char dynsm[];
    u32 raw = smem_u32(dynsm);
    u32 sb = (raw + 127u) & ~127u;
    float* Sm = (float*)(dynsm + (sb - raw) + NST * STG);
    u32 sbar = sb + NST * STG + 16640;   // full[8] @0, empty[8] @64

    const int tid  = threadIdx.x;
    const int wid  = tid >> 5;
    const int lane = tid & 31;
    const int bid  = blockIdx.x;
    const int nt   = bid >> 1;
    const int kh   = bid & 1;
    const int j0   = nt * 16;
    const int mt   = wid >> 2;
    const int nq   = wid & 3;
    const int m0   = mt * 16;
    const int nb   = nq * 16;

    if (tid == 0) {
#pragma unroll
        for (int s = 0; s < NST; s++) {
            mbar_init(sbar + s * 8, 1);
            mbar_init(sbar + 64 + s * 8, 16);
        }
    }
    __syncthreads();

    u32 gg = 0;

    for (int w = 0; w < TT + 2; w++) {
        Seg segs[3];
        int ns = 0, total = 0;
#pragma unroll
        for (int l = 0; l < 3; l++) {
            int t = w - l;
            if (t >= 0 && t < TT) {
                make_seg(segs[ns], l, t, nt, kh);
                segs[ns].start = total;
                total += segs[ns].nch;
                ns++;
            }
        }

        if (tid == 0) {
#pragma unroll
            for (int i = 0; i < NST - 1; i++)
                if (i < total) issue_chunk(sb, sbar, segs, ns, i, gg);
        }

        float acc[3][2][4];
#pragma unroll
        for (int s = 0; s < 3; s++)
#pragma unroll
            for (int i = 0; i < 2; i++)
#pragma unroll
                for (int q = 0; q < 4; q++) acc[s][i][q] = 0.f;

        int g = 0;
        for (int s = 0; s < ns; s++) {
            const int nch = segs[s].nch;

            u32 af[2][4], bf[2][4];
            {
                u32 gc = gg + (u32)g;
                u32 cur = gc & (NST - 1u);
                mbar_wait(sbar + cur * 8, (gc >> 3) & 1u);
                u32 At = sb + cur * STG;
                ldm4(ldm_addr(At, m0, 0, lane), af[0]);
                ldm4(ldm_addr(At + 8192, nb, 0, lane), bf[0]);
            }

            int p = 0;
            for (int c = 0; c < nch; c++) {
                u32 gc  = gg + (u32)g;
                u32 cur = gc & (NST - 1u);

                if (tid == 0 && g + NST - 1 < total)
                    issue_chunk(sb, sbar, segs, ns, g + NST - 1, gg);

#pragma unroll
                for (int kq = 0; kq < 4; kq++) {
                    if (kq < 3) {
                        u32 At = sb + cur * STG;
                        ldm4(ldm_addr(At, m0, kq + 1, lane), af[p ^ 1]);
                        ldm4(ldm_addr(At + 8192, nb, kq + 1, lane), bf[p ^ 1]);
                    } else if (c + 1 < nch) {
                        u32 gn  = gc + 1;
                        u32 nxt = gn & (NST - 1u);
                        mbar_wait(sbar + nxt * 8, (gn >> 3) & 1u);
                        u32 At = sb + nxt * STG;
                        ldm4(ldm_addr(At, m0, 0, lane), af[p ^ 1]);
                        ldm4(ldm_addr(At + 8192, nb, 0, lane), bf[p ^ 1]);
                    }
                    mma16816(acc[s][0], af[p], bf[p][0], bf[p][2]);
                    mma16816(acc[s][1], af[p], bf[p][1], bf[p][3]);
                    if (kq == 3 && lane == 0) mbar_arrive(sbar + 64 + cur * 8);
                    p ^= 1;
                }
                g++;
            }

            const int owner = (segs[s].l == 1) ? 1 : 0;
            if (kh != owner) {
                float4* pp4 = (float4*)(g_part + ((size_t)segs[s].l * 64 + nt) * 4096);
#pragma unroll
                for (int nti = 0; nti < 2; nti++) {
                    float4 v = make_float4(acc[s][nti][0], acc[s][nti][1],
                                           acc[s][nti][2], acc[s][nti][3]);
                    __stcg(&pp4[tid * 2 + nti], v);
                }
            }
        }

        __threadfence();
        __syncthreads();
        if (tid == 0) {
            for (int s = 0; s < ns; s++) {
                const int owner = (segs[s].l == 1) ? 1 : 0;
                if (kh != owner)
                    atomicExch(&g_flag[segs[s].l * 64 + nt], (unsigned)(segs[s].t + 1));
            }
        }

        for (int s = 0; s < ns; s++) {
            const int l = segs[s].l;
            const int t = segs[s].t;
            const int owner = (l == 1) ? 1 : 0;
            if (kh != owner) continue;

            unsigned* flag = &g_flag[l * 64 + nt];
            if (tid == 0) {
                while (*(volatile unsigned*)flag != (unsigned)(t + 1)) __nanosleep(16);
                __threadfence();
            }
            __syncthreads();

            const float4* pp4 = (const float4*)(g_part + ((size_t)l * 64 + nt) * 4096);
#pragma unroll
            for (int nti = 0; nti < 2; nti++) {
                float4 v = __ldcg(&pp4[tid * 2 + nti]);
                acc[s][nti][0] += v.x; acc[s][nti][1] += v.y;
                acc[s][nti][2] += v.z; acc[s][nti][3] += v.w;
            }
            {
                int gid = lane >> 2, tig = lane & 3;
                int mrow = m0 + gid;
#pragma unroll
                for (int nti = 0; nti < 2; nti++) {
                    int cc = nb + nti * 8 + tig * 2;
                    Sm[cc * 65 + mrow]           = acc[s][nti][0];
                    Sm[(cc + 1) * 65 + mrow]     = acc[s][nti][1];
                    Sm[cc * 65 + mrow + 8]       = acc[s][nti][2];
                    Sm[(cc + 1) * 65 + mrow + 8] = acc[s][nti][3];
                }
            }
            __syncthreads();

            const float* bias = (l == 0) ? b1 : (l == 1) ? b2 : b3;
            float* cbuf = g_c[l];
            unsigned char* imgout = (l == 0) ? g_img1[(t + 1) & 1]
                                  : (l == 1) ? g_img2[(t + 1) & 1]
                                             : g_img3[(t + 1) & 1];
#pragma unroll
            for (int i = 0; i < 2; i++) {
                int e  = tid + i * 512;
                int m  = e & 63;
                int jj = e >> 6;
                int jg = j0 + jj;
                float f  = Sm[jj * 65 + m]        + bias[jg];
                float ig = Sm[(16 + jj) * 65 + m] + bias[HH + jg];
                float og = Sm[(32 + jj) * 65 + m] + bias[2 * HH + jg];
                float ct = Sm[(48 + jj) * 65 + m] + bias[3 * HH + jg];
                if (l == 0) {
                    int xid = X[m * TT + t];
                    const float* wrow = W1 + (size_t)xid * GG + jg;
                    f  += wrow[0];
                    ig += wrow[HH];
                    og += wrow[2 * HH];
                    ct += wrow[3 * HH];
                }
                int cidx = m * HH + jg;
                float cv = cbuf[cidx];
                float sf = 1.f / (1.f + __expf(-f));
                float si = 1.f / (1.f + __expf(-ig));
                float so = 1.f / (1.f + __expf(-og));
                float cn = sf * cv + si * tanhf(ct);
                float hn = so * tanhf(cn);
                cbuf[cidx] = cn;

                __half hv = __float2half(hn);
                u32 off = swz((u32)(m * 128 + (jg & 63) * 2));
                unsigned char* cb = imgout + (size_t)(jg >> 6) * 8192;
                *(__half*)(cb + off) = hv;

                if (l == 2) {
                    // h3 fp16 MMA-tile image for the deferred output GEMM
                    unsigned char* hb = g_h3img + ((size_t)t * 16 + (size_t)(jg >> 6)) * 8192;
                    *(__half*)(hb + off) = hv;
                    if (t == TT - 1) g_hfin3[cidx] = hn;
                } else if (t == TT - 1) {
                    g_hfin[l][cidx] = hn;
                }
            }
            __syncthreads();
        }

        gg += (u32)total;
        gbar();
    }
}

// ---------------- out GEMM v2 (fp16 mma.sync): out = H3img @ WoutImg + bout ----------------
__global__ void __launch_bounds__(256) out_gemm2(
    const float* __restrict__ bout, float* __restrict__ out)
{
    __shared__ __align__(1024) unsigned char smbuf[2][16384];   // [stage][A 8K | W 8K]
    const int tid  = threadIdx.x;
    const int wid  = tid >> 5;
    const int lane = tid & 31;
    const int ntb  = blockIdx.x;   // 0..31  (64 vocab cols each)
    const int mtb  = blockIdx.y;   // 0..255 (= timestep t; 64 batch rows)
    const int mt   = wid >> 1;     // 0..3
    const int nh   = wid & 1;      // 0..1
    const int m0   = mt * 16;
    const int nb   = nh * 32;

    const unsigned char* ab = g_h3img + (size_t)mtb * (16 * 8192);
    const unsigned char* wb = g_woimg + (size_t)ntb * (16 * 8192);
    u32 smb = smem_u32(smbuf);

    // stage 0
    cp16(smb + tid * 16,         ab + tid * 16);
    cp16(smb + 4096 + tid * 16,  ab + 4096 + (size_t)tid * 16);
    cp16(smb + 8192 + tid * 16,  wb + tid * 16);
    cp16(smb + 12288 + tid * 16, wb + 4096 + (size_t)tid * 16);
    cp_commit();

    float acc[4][4];
#pragma unroll
    for (int i = 0; i < 4; i++)
#pragma unroll
        for (int q = 0; q < 4; q++) acc[i][q] = 0.f;

    for (int c = 0; c < 16; c++) {
        if (c + 1 < 16) {
            u32 d = smb + (u32)((c + 1) & 1) * 16384;
            const unsigned char* a2 = ab + (size_t)(c + 1) * 8192;
            const unsigned char* w2 = wb + (size_t)(c + 1) * 8192;
            cp16(d + tid * 16,         a2 + tid * 16);
            cp16(d + 4096 + tid * 16,  a2 + 4096 + (size_t)tid * 16);
            cp16(d + 8192 + tid * 16,  w2 + tid * 16);
            cp16(d + 12288 + tid * 16, w2 + 4096 + (size_t)tid * 16);
            cp_commit();
            cp_wait1();
        } else {
            cp_wait0();
        }
        __syncthreads();

        u32 At = smb + (u32)(c & 1) * 16384;
        u32 Wt = At + 8192;
#pragma unroll
        for (int kq = 0; kq < 4; kq++) {
            u32 a[4], b0[4], b1[4];
            ldm4(ldm_addr(At, m0, kq, lane), a);
            ldm4(ldm_addr(Wt, nb, kq, lane), b0);
            ldm4(ldm_addr(Wt, nb + 16, kq, lane), b1);
            mma16816(acc[0], a, b0[0], b0[2]);
            mma16816(acc[1], a, b0[1], b0[3]);
            mma16816(acc[2], a, b1[0], b1[2]);
            mma16816(acc[3], a, b1[1], b1[3]);
        }
        __syncthreads();
    }

    // epilogue
    int gid = lane >> 2, tig = lane & 3;
    int row  = mtb * 64 + m0 + gid;
    int colb = ntb * 64 + nb;
#pragma unroll
    for (int nti = 0; nti < 4; nti++) {
        int col = colb + nti * 8 + tig * 2;
        float bo0 = bout[col], bo1 = bout[col + 1];
        out[(size_t)row * VV + col]           = acc[nti][0] + bo0;
        out[(size_t)row * VV + col + 1]       = acc[nti][1] + bo1;
        out[(size_t)(row + 8) * VV + col]     = acc[nti][2] + bo0;
        out[(size_t)(row + 8) * VV + col + 1] = acc[nti][3] + bo1;
    }
}

__global__ void copy_states(float* __restrict__ out) {
    int i = blockIdx.x * blockDim.x + threadIdx.x;
    if (i < BB * HH) {
        out[0 * BB * HH + i] = g_hfin[0][i];
        out[1 * BB * HH + i] = g_c[0][i];
        out[2 * BB * HH + i] = g_hfin[1][i];
        out[3 * BB * HH + i] = g_c[1][i];
        out[4 * BB * HH + i] = g_hfin3[i];
        out[5 * BB * HH + i] = g_c[2][i];
    }
}

// ---------------- launch ----------------
extern "C" void kernel_launch(void* const* d_in, const int* in_sizes, int n_in,
                              void* d_out, int out_size) {
    const int*   X    = (const int*)  d_in[0];
    const float* W1   = (const float*)d_in[1];
    const float* b1   = (const float*)d_in[2];
    const float* W2   = (const float*)d_in[3];
    const float* b2   = (const float*)d_in[4];
    const float* W3   = (const float*)d_in[5];
    const float* b3   = (const float*)d_in[6];
    const float* Wout = (const float*)d_in[7];
    const float* bout = (const float*)d_in[8];
    float* out = (float*)d_out;
    (void)in_sizes; (void)n_in;

    static int attr_done = 0;
    if (!attr_done) {
        cudaFuncSetAttribute(lstm_persist, cudaFuncAttributeMaxDynamicSharedMemorySize, 148224);
        attr_done = 1;
    }

    init_zero<<<256, 256>>>();

    dim3 wgrid((2u * HH * GG + 255) / 256, 4);
    wconv<<<wgrid, 256>>>(W1, W2, W3, Wout);

    lstm_persist<<<NBLK, NTHR, 148224>>>(X, W1, b1, b2, b3);

    dim3 out_grid(VV / 64, TT);
    out_gemm2<<<out_grid, 256>>>(bout, out);

    long long need = (long long)TT * BB * VV + 6LL * BB * HH;
    if ((long long)out_size >= need) {
        copy_states<<<(BB * HH + 255) / 256, 256>>>(out + (size_t)TT * BB * VV);
    }
}